// round 8
// baseline (speedup 1.0000x reference)
#include <cuda_runtime.h>
#include <cuda_fp16.h>
#include <math.h>
#include <stdint.h>

#define DIMS 1024
#define FFD  4096
#define BATCH 4
#define SEQ  4096
#define ROWS (BATCH*SEQ)   // 16384
#define NF   513           // rfft bins for N=1024

// ---------------- scratch (device globals; no allocation allowed) ----------------
__device__ float  g_qk [(size_t)ROWS*2*DIMS];   // q | k packed (N=2048 GEMM out)
__device__ float  g_x1 [(size_t)ROWS*DIMS];     // LN output (residual, fp32)
__device__ __half g_x1h[(size_t)ROWS*DIMS];     // fp16 copy (GEMM input)
__device__ float  g_ff [(size_t)ROWS*DIMS];
__device__ __half g_h  [(size_t)ROWS*FFD];      // FFN hidden, fp16
__device__ __half g_xh [(size_t)ROWS*DIMS];     // x in fp16
__device__ __half g_wh [(size_t)(2*DIMS*DIMS + 2*DIMS*FFD)]; // Wqk | W1 | W2 fp16
__device__ float  g_br [2*DIMS];                // bq | bk packed
__device__ float2 g_kx[(size_t)ROWS*NF];
__device__ float2 g_qf[(size_t)ROWS*NF];
__device__ float2 g_sf[BATCH*NF];

#define WQK_OFF 0
#define W1_OFF  (2*DIMS*DIMS)
#define W2_OFF  (2*DIMS*DIMS + DIMS*FFD)

// ---------------- PTX helpers ----------------
__device__ __forceinline__ uint32_t smem_u32(const void* p) {
    uint32_t a;
    asm("{ .reg .u64 t; cvta.to.shared.u64 t, %1; cvt.u32.u64 %0, t; }" : "=r"(a) : "l"(p));
    return a;
}
__device__ __forceinline__ uint32_t h2_as_u32(__half2 h) {
    union { __half2 h; uint32_t u; } cvt;
    cvt.h = h;
    return cvt.u;
}
__device__ __forceinline__ void cp16(uint32_t dst, const void* src) {
    asm volatile("cp.async.cg.shared.global [%0], [%1], 16;" :: "r"(dst), "l"(src));
}
#define CP_COMMIT() asm volatile("cp.async.commit_group;" ::: "memory")
template<int N> __device__ __forceinline__ void cp_wait() {
    asm volatile("cp.async.wait_group %0;" :: "n"(N) : "memory");
}
__device__ __forceinline__ void mma_f16(float& c0, float& c1, float& c2, float& c3,
                                        uint32_t a0, uint32_t a1, uint32_t a2, uint32_t a3,
                                        uint32_t b0, uint32_t b1) {
    asm volatile(
        "mma.sync.aligned.m16n8k16.row.col.f32.f16.f16.f32 "
        "{%0,%1,%2,%3}, {%4,%5,%6,%7}, {%8,%9}, {%0,%1,%2,%3};"
        : "+f"(c0), "+f"(c1), "+f"(c2), "+f"(c3)
        : "r"(a0), "r"(a1), "r"(a2), "r"(a3), "r"(b0), "r"(b1));
}
__device__ __forceinline__ void ldsm_x4(uint32_t& r0, uint32_t& r1, uint32_t& r2, uint32_t& r3,
                                        uint32_t addr) {
    asm volatile("ldmatrix.sync.aligned.m8n8.x4.shared.b16 {%0,%1,%2,%3}, [%4];"
                 : "=r"(r0), "=r"(r1), "=r"(r2), "=r"(r3) : "r"(addr));
}

// ---------------- fp32 -> fp16 convert pre-passes ----------------
__global__ void __launch_bounds__(256) conv_h_kernel(const float* __restrict__ src,
                                                     __half* __restrict__ dst, int n8) {
    int i = blockIdx.x * 256 + threadIdx.x;
    if (i < n8) {
        float4 a = ((const float4*)src)[2*i];
        float4 b = ((const float4*)src)[2*i+1];
        uint4 o;
        o.x = h2_as_u32(__floats2half2_rn(a.x, a.y));
        o.y = h2_as_u32(__floats2half2_rn(a.z, a.w));
        o.z = h2_as_u32(__floats2half2_rn(b.x, b.y));
        o.w = h2_as_u32(__floats2half2_rn(b.z, b.w));
        ((uint4*)dst)[i] = o;
    }
}
__global__ void pack_bias_kernel(const float* __restrict__ bq, const float* __restrict__ bk) {
    int i = blockIdx.x * 256 + threadIdx.x;
    if (i < DIMS) { g_br[i] = bq[i]; g_br[i + DIMS] = bk[i]; }
}

// ======================= mma.sync fp16 GEMM =======================
// C[M,N] = A[M,K]*B[N,K]^T + bias. A,B fp16 K-contiguous.
// 256x128x64 CTA tile, 256 threads (8 warps = 4M x 2N, warp tile 64x64),
// 3-stage cp.async pipeline, padded row stride 144 B. mblk: M-block offset.
#define BK 64
#define ROWB 144
#define A_TILE_BYTES (256*ROWB)                  // 36864
#define B_TILE_BYTES (128*ROWB)                  // 18432
#define STAGE_BYTES (A_TILE_BYTES + B_TILE_BYTES) // 55296
#define NSTAGE 3

template<int RELU, typename CT>
__global__ void __launch_bounds__(256, 1)
gemm_h(const __half* __restrict__ A, const __half* __restrict__ B,
       const float* __restrict__ bias, CT* __restrict__ C,
       int N, int K, int mblk)
{
    extern __shared__ char smem[];
    const int tid = threadIdx.x;
    const int warp = tid >> 5;
    const int lane = tid & 31;
    const int wm = warp >> 1;
    const int wn = warp & 1;
    const int lr = lane >> 2;
    const int lc = lane & 3;
    const int mb = blockIdx.y + mblk;

    const __half* Ab = A + (size_t)mb * 256 * K;
    const __half* Bb = B + (size_t)blockIdx.x * 128 * K;

    const uint32_t sbase = smem_u32(smem);
    const int ktiles = K / BK;

    uint32_t aoff[4];
    {
        const int l7 = lane & 7;
        const int rsel = (lane >> 3) & 1;
        const int csel = lane >> 4;
        #pragma unroll
        for (int mt = 0; mt < 4; mt++) {
            int r = wm * 64 + mt * 16 + l7 + rsel * 8;
            aoff[mt] = (uint32_t)(r * ROWB + csel * 16);
        }
    }
    uint32_t boff[4];
    {
        const int l7 = lane & 7;
        const int csel = (lane >> 3) & 1;
        const int rsel = lane >> 4;
        #pragma unroll
        for (int pr = 0; pr < 4; pr++) {
            int r = wn * 64 + pr * 16 + rsel * 8 + l7;
            boff[pr] = (uint32_t)(r * ROWB + csel * 16);
        }
    }

    auto load_stage = [&](int stage, int kt) {
        const int k0 = kt * BK;
        const uint32_t sA = sbase + stage * STAGE_BYTES;
        const uint32_t sB = sA + A_TILE_BYTES;
        #pragma unroll
        for (int i = 0; i < 8; i++) {
            int g = i * 256 + tid;
            int r = g >> 3, c = g & 7;
            cp16(sA + r * ROWB + c * 16, Ab + (size_t)r * K + k0 + c * 8);
        }
        #pragma unroll
        for (int i = 0; i < 4; i++) {
            int g = i * 256 + tid;
            int r = g >> 3, c = g & 7;
            cp16(sB + r * ROWB + c * 16, Bb + (size_t)r * K + k0 + c * 8);
        }
    };

    load_stage(0, 0); CP_COMMIT();
    load_stage(1, 1); CP_COMMIT();

    float acc[4][8][4];
    #pragma unroll
    for (int i = 0; i < 4; i++)
        #pragma unroll
        for (int j = 0; j < 8; j++)
            #pragma unroll
            for (int r = 0; r < 4; r++) acc[i][j][r] = 0.f;

    for (int it = 0; it < ktiles; it++) {
        cp_wait<1>();
        __syncthreads();

        const uint32_t sA = sbase + (it % NSTAGE) * STAGE_BYTES;
        const uint32_t sB = sA + A_TILE_BYTES;

        const int nt2 = it + 2;
        if (nt2 < ktiles) load_stage(nt2 % NSTAGE, nt2);
        CP_COMMIT();

        #pragma unroll
        for (int ks = 0; ks < 4; ks++) {
            const uint32_t kb = ks * 32;
            uint32_t a[4][4], b[8][2];
            #pragma unroll
            for (int mt = 0; mt < 4; mt++)
                ldsm_x4(a[mt][0], a[mt][1], a[mt][2], a[mt][3], sA + aoff[mt] + kb);
            #pragma unroll
            for (int pr = 0; pr < 4; pr++)
                ldsm_x4(b[2*pr][0], b[2*pr][1], b[2*pr+1][0], b[2*pr+1][1],
                        sB + boff[pr] + kb);
            #pragma unroll
            for (int mt = 0; mt < 4; mt++)
                #pragma unroll
                for (int nt = 0; nt < 8; nt++)
                    mma_f16(acc[mt][nt][0], acc[mt][nt][1],
                            acc[mt][nt][2], acc[mt][nt][3],
                            a[mt][0], a[mt][1], a[mt][2], a[mt][3],
                            b[nt][0], b[nt][1]);
        }
        __syncthreads();
    }

    // epilogue
    const int crow0 = mb * 256 + wm * 64;
    const int ccol0 = blockIdx.x * 128 + wn * 64;
    float bb0[8], bb1[8];
    #pragma unroll
    for (int nt = 0; nt < 8; nt++) {
        bb0[nt] = __ldg(bias + ccol0 + nt * 8 + lc * 2);
        bb1[nt] = __ldg(bias + ccol0 + nt * 8 + lc * 2 + 1);
    }
    #pragma unroll
    for (int mt = 0; mt < 4; mt++) {
        #pragma unroll
        for (int nt = 0; nt < 8; nt++) {
            const int r0 = crow0 + mt * 16 + lr;
            const int c0 = ccol0 + nt * 8 + lc * 2;
            float v0 = acc[mt][nt][0] + bb0[nt];
            float v1 = acc[mt][nt][1] + bb1[nt];
            float v2 = acc[mt][nt][2] + bb0[nt];
            float v3 = acc[mt][nt][3] + bb1[nt];
            if (RELU) {
                v0 = fmaxf(v0, 0.f); v1 = fmaxf(v1, 0.f);
                v2 = fmaxf(v2, 0.f); v3 = fmaxf(v3, 0.f);
            }
            if (sizeof(CT) == 2) {
                *(__half2*)((__half*)C + (size_t)r0 * N + c0)       = __floats2half2_rn(v0, v1);
                *(__half2*)((__half*)C + (size_t)(r0 + 8) * N + c0) = __floats2half2_rn(v2, v3);
            } else {
                *(float2*)((float*)C + (size_t)r0 * N + c0)       = make_float2(v0, v1);
                *(float2*)((float*)C + (size_t)(r0 + 8) * N + c0) = make_float2(v2, v3);
            }
        }
    }
}

// ---------------- FFT path helpers ----------------
__device__ __forceinline__ float2 cmulf(float2 a, float2 b) {
    return make_float2(a.x*b.x - a.y*b.y, a.x*b.y + a.y*b.x);
}
#define F(i) ((i) ^ ((((i) >> 5) & 7) << 2))

__device__ __forceinline__ float2 block_sum2_256(float2 v, volatile float2* red) {
    int t = threadIdx.x;
    #pragma unroll
    for (int o = 16; o; o >>= 1) {
        v.x += __shfl_xor_sync(0xffffffffu, v.x, o);
        v.y += __shfl_xor_sync(0xffffffffu, v.y, o);
    }
    if ((t & 31) == 0) { red[t >> 5].x = v.x; red[t >> 5].y = v.y; }
    __syncthreads();
    if (t == 0) {
        float2 s = make_float2(0.f, 0.f);
        #pragma unroll
        for (int i = 0; i < 8; i++) { s.x += red[i].x; s.y += red[i].y; }
        red[0].x = s.x; red[0].y = s.y;
    }
    __syncthreads();
    float2 r = make_float2(red[0].x, red[0].y);
    __syncthreads();
    return r;
}

// 1024-pt radix-4 Stockham FFT (forward), 256 threads, 5 stages. Result in bufB.
__device__ __forceinline__ void fft1024_r4(float2* bufA, float2* bufB,
                                           const float2* tw, int v) {
    float2* src = bufA; float2* dst = bufB;
    #pragma unroll
    for (int st = 0; st < 5; st++) {
        const int ls = 2 * st;
        const int s = 1 << ls;
        const int idx = v & ~(s - 1);
        float2 w1 = tw[idx];
        float2 w2 = tw[2*idx];
        float2 w3 = tw[3*idx];
        float2 a = src[F(v)];
        float2 b = src[F(v + 256)];
        float2 c = src[F(v + 512)];
        float2 d = src[F(v + 768)];
        float2 apc = make_float2(a.x + c.x, a.y + c.y);
        float2 amc = make_float2(a.x - c.x, a.y - c.y);
        float2 bpd = make_float2(b.x + d.x, b.y + d.y);
        float2 jbmd = make_float2(-(b.y - d.y), b.x - d.x);
        const int bo = v + 3 * idx;
        dst[F(bo)]         = make_float2(apc.x + bpd.x, apc.y + bpd.y);
        dst[F(bo + s)]     = cmulf(w1, make_float2(amc.x - jbmd.x, amc.y - jbmd.y));
        dst[F(bo + 2*s)]   = cmulf(w2, make_float2(apc.x - bpd.x, apc.y - bpd.y));
        dst[F(bo + 3*s)]   = cmulf(w3, make_float2(amc.x + jbmd.x, amc.y + jbmd.y));
        __syncthreads();
        float2* tmp = src; src = dst; dst = tmp;
    }
}

// ---------------- forward FFTs: LN(q), LN(k); Kx = Xf*Kf; Qf ----------------
__global__ void __launch_bounds__(256) fft_fwd_kernel(
    const float* __restrict__ x,
    const float* __restrict__ gq, const float* __restrict__ betaq,
    const float* __restrict__ gk, const float* __restrict__ betak, int roff)
{
    const int row = blockIdx.x + roff;
    const int t = threadIdx.x;
    __shared__ float2 tw[768];
    __shared__ float2 bufA[1024];
    __shared__ float2 bufB[1024];
    __shared__ float2 red2[8];

    #pragma unroll
    for (int j = 0; j < 3; j++) {
        int i = t + 256 * j;
        float s_, c_;
        sincospif((float)i * (1.0f/512.0f), &s_, &c_);
        tw[i] = make_float2(c_, -s_);
    }

    const float* xr = x    + (size_t)row * DIMS;
    const float* qr = g_qk + (size_t)row * 2 * DIMS;
    const float* kr = qr + DIMS;
    float xv[4], qv[4], kv[4];
    #pragma unroll
    for (int i = 0; i < 4; i++) {
        int e = t + 256 * i;
        xv[i] = xr[e]; qv[i] = qr[e]; kv[i] = kr[e];
    }

    const float invN = 1.0f / 1024.0f;
    float2 s1 = make_float2(0.f, 0.f), s2 = make_float2(0.f, 0.f);
    #pragma unroll
    for (int i = 0; i < 4; i++) {
        s1.x += qv[i]; s1.y += kv[i];
        s2.x += qv[i]*qv[i]; s2.y += kv[i]*kv[i];
    }
    s1 = block_sum2_256(s1, red2);
    s2 = block_sum2_256(s2, red2);
    float mq = s1.x * invN, vq = s2.x * invN - mq*mq;
    float rq = rsqrtf(vq + 1e-5f);
    float mk = s1.y * invN, vk = s2.y * invN - mk*mk;
    float rk = rsqrtf(vk + 1e-5f);

    float qn[4], kn[4];
    #pragma unroll
    for (int i = 0; i < 4; i++) {
        int e = t + 256 * i;
        qn[i] = (qv[i] - mq) * rq * gq[e] + betaq[e];
        kn[i] = (kv[i] - mk) * rk * gk[e] + betak[e];
    }

    #pragma unroll
    for (int i = 0; i < 4; i++) bufA[F(t + 256*i)] = make_float2(xv[i], kn[i]);
    __syncthreads();
    fft1024_r4(bufA, bufB, tw, t);

    {
        #pragma unroll
        for (int jj = 0; jj < 2; jj++) {
            int j = t + 256 * jj;
            float2 z  = bufB[F(j)];
            float2 zn = bufB[F((1024 - j) & 1023)];
            float2 xf = make_float2(0.5f*(z.x + zn.x), 0.5f*(z.y - zn.y));
            float2 df = make_float2(z.x - zn.x, z.y + zn.y);
            float2 kf = make_float2(0.5f*df.y, -0.5f*df.x);
            g_kx[(size_t)row*NF + j] = cmulf(xf, kf);
        }
        if (t == 0) {
            float2 z5 = bufB[F(512)];
            g_kx[(size_t)row*NF + 512] = make_float2(z5.x * z5.y, 0.f);
        }
    }
    #pragma unroll
    for (int i = 0; i < 4; i++) bufA[F(t + 256*i)] = make_float2(qn[i], 0.f);
    __syncthreads();
    fft1024_r4(bufA, bufB, tw, t);

    #pragma unroll
    for (int jj = 0; jj < 2; jj++) {
        int j = t + 256 * jj;
        g_qf[(size_t)row*NF + j] = bufB[F(j)];
    }
    if (t == 0) g_qf[(size_t)row*NF + 512] = bufB[F(512)];
}

// ---------------- reduce S_freq[b] = sum_s Kx[b,s]  (coalesced) ----------------
__global__ void __launch_bounds__(256) reduce_s_kernel() {
    const int b  = blockIdx.x;          // batch
    const int jc = blockIdx.y;          // 0..8  (64 bins each)
    const int t  = threadIdx.x;
    const int jl = t & 63;
    const int sl = t >> 6;              // 0..3
    const int j  = jc * 64 + jl;
    float2 acc = make_float2(0.f, 0.f);
    if (j < NF) {
        const float2* p = g_kx + (size_t)b * SEQ * NF + j;
        for (int s = sl; s < SEQ; s += 4) {
            float2 v = p[(size_t)s * NF];
            acc.x += v.x; acc.y += v.y;
        }
    }
    __shared__ float2 red[256];
    red[t] = acc;
    __syncthreads();
    if (t < 128) { red[t].x += red[t+128].x; red[t].y += red[t+128].y; }
    __syncthreads();
    if (t < 64) {
        red[t].x += red[t+64].x; red[t].y += red[t+64].y;
        if (j < NF) g_sf[b * NF + j] = red[t];
    }
}

// ---------------- inverse FFT of mixF = Kx + S*conj(Qf); LN(x + mix) ----------------
__global__ void __launch_bounds__(256) fft_inv_ln_kernel(
    const float* __restrict__ x,
    const float* __restrict__ g0, const float* __restrict__ beta0, int roff)
{
    const int row = blockIdx.x + roff;
    const int b = row >> 12;
    const int t = threadIdx.x;
    __shared__ float2 tw[768];
    __shared__ float2 bufA[1024];
    __shared__ float2 bufB[1024];
    __shared__ float2 red2[8];

    #pragma unroll
    for (int j = 0; j < 3; j++) {
        int i = t + 256 * j;
        float s_, c_;
        sincospif((float)i * (1.0f/512.0f), &s_, &c_);
        tw[i] = make_float2(c_, -s_);
    }

    #pragma unroll
    for (int jj = 0; jj < 2; jj++) {
        int j = t + 256 * jj;
        float2 kx = g_kx[(size_t)row*NF + j];
        float2 sf = g_sf[b*NF + j];
        float2 qf = g_qf[(size_t)row*NF + j];
        float2 qc = make_float2(qf.x, -qf.y);
        float2 p  = cmulf(sf, qc);
        float2 mv = make_float2(kx.x + p.x, kx.y + p.y);
        bufA[F(j)] = make_float2(mv.x, -mv.y);
        if (j > 0) bufA[F(1024 - j)] = mv;
    }
    if (t == 0) {
        float2 kx5 = g_kx[(size_t)row*NF + 512];
        float2 sf5 = g_sf[b*NF + 512];
        float2 qf5 = g_qf[(size_t)row*NF + 512];
        float2 qc5 = make_float2(qf5.x, -qf5.y);
        float2 p5  = cmulf(sf5, qc5);
        bufA[F(512)] = make_float2(kx5.x + p5.x, -(kx5.y + p5.y));
    }
    __syncthreads();
    fft1024_r4(bufA, bufB, tw, t);

    const float invN = 1.0f / 1024.0f;
    const float* xr = x + (size_t)row * DIMS;
    float y[4];
    float2 s12 = make_float2(0.f, 0.f);
    #pragma unroll
    for (int i = 0; i < 4; i++) {
        int e = t + 256 * i;
        y[i] = xr[e] + bufB[F(e)].x * invN;
        s12.x += y[i];
        s12.y += y[i] * y[i];
    }
    s12 = block_sum2_256(s12, red2);
    float m = s12.x * invN, v = s12.y * invN - m*m;
    float r = rsqrtf(v + 1e-5f);
    float*  o  = g_x1  + (size_t)row * DIMS;
    __half* oh = g_x1h + (size_t)row * DIMS;
    #pragma unroll
    for (int i = 0; i < 4; i++) {
        int e = t + 256 * i;
        float ov = (y[i] - m) * r * g0[e] + beta0[e];
        o[e]  = ov;
        oh[e] = __float2half_rn(ov);
    }
}

// ---------------- out = LN(x1 + ff) ----------------
__device__ __forceinline__ float block_sum512(float v, volatile float* red) {
    int t = threadIdx.x;
    #pragma unroll
    for (int o = 16; o; o >>= 1) v += __shfl_xor_sync(0xffffffffu, v, o);
    if ((t & 31) == 0) red[t >> 5] = v;
    __syncthreads();
    if (t == 0) {
        float s = 0.f;
        #pragma unroll
        for (int i = 0; i < 16; i++) s += red[i];
        red[0] = s;
    }
    __syncthreads();
    float r = red[0];
    __syncthreads();
    return r;
}

__global__ void __launch_bounds__(512) resid_ln_kernel(
    const float* __restrict__ g1v, const float* __restrict__ beta1,
    float* __restrict__ out, int roff)
{
    const int row = blockIdx.x + roff;
    const int t = threadIdx.x;
    __shared__ float red[16];
    const float* a = g_x1 + (size_t)row * DIMS;
    const float* f = g_ff + (size_t)row * DIMS;
    float y0 = a[t]     + f[t];
    float y1 = a[t+512] + f[t+512];
    const float invN = 1.0f / 1024.0f;
    float s  = block_sum512(y0 + y1, red);
    float ss = block_sum512(y0*y0 + y1*y1, red);
    float m = s * invN, v = ss * invN - m*m;
    float r = rsqrtf(v + 1e-5f);
    float* o = out + (size_t)row * DIMS;
    o[t]     = (y0 - m) * r * g1v[t]     + beta1[t];
    o[t+512] = (y1 - m) * r * g1v[t+512] + beta1[t+512];
}

// ---------------- launch ----------------
extern "C" void kernel_launch(void* const* d_in, const int* in_sizes, int n_in,
                              void* d_out, int out_size)
{
    const float* x     = (const float*)d_in[0];
    const float* Wq    = (const float*)d_in[1];
    const float* bq    = (const float*)d_in[2];
    const float* gq    = (const float*)d_in[3];
    const float* betaq = (const float*)d_in[4];
    const float* Wk    = (const float*)d_in[5];
    const float* bk    = (const float*)d_in[6];
    const float* gk    = (const float*)d_in[7];
    const float* betak = (const float*)d_in[8];
    const float* g0    = (const float*)d_in[9];
    const float* beta0 = (const float*)d_in[10];
    const float* W1    = (const float*)d_in[11];
    const float* b1    = (const float*)d_in[12];
    const float* W2    = (const float*)d_in[13];
    const float* b2    = (const float*)d_in[14];
    const float* g1    = (const float*)d_in[15];
    const float* beta1 = (const float*)d_in[16];
    float* out = (float*)d_out;

    float *pqk, *pff, *pbr;
    __half *px1h, *ph, *pxh, *pwh;
    cudaGetSymbolAddress((void**)&pqk,  g_qk);
    cudaGetSymbolAddress((void**)&px1h, g_x1h);
    cudaGetSymbolAddress((void**)&ph,   g_h);
    cudaGetSymbolAddress((void**)&pff,  g_ff);
    cudaGetSymbolAddress((void**)&pxh,  g_xh);
    cudaGetSymbolAddress((void**)&pwh,  g_wh);
    cudaGetSymbolAddress((void**)&pbr,  g_br);

    const int SMEM = NSTAGE * STAGE_BYTES;  // 165888 B
    cudaFuncSetAttribute(gemm_h<0,float>,  cudaFuncAttributeMaxDynamicSharedMemorySize, SMEM);
    cudaFuncSetAttribute(gemm_h<1,__half>, cudaFuncAttributeMaxDynamicSharedMemorySize, SMEM);

    // aux stream + events (created per call; capture-legal, leaked on purpose)
    cudaStream_t s1;
    cudaStreamCreate(&s1);
    cudaEvent_t eFork, eW, eG1a, eG1b, eFa, eFb, eRed, eIb, eG3a, eJoin;
    cudaEventCreateWithFlags(&eFork, cudaEventDisableTiming);
    cudaEventCreateWithFlags(&eW,    cudaEventDisableTiming);
    cudaEventCreateWithFlags(&eG1a,  cudaEventDisableTiming);
    cudaEventCreateWithFlags(&eG1b,  cudaEventDisableTiming);
    cudaEventCreateWithFlags(&eFa,   cudaEventDisableTiming);
    cudaEventCreateWithFlags(&eFb,   cudaEventDisableTiming);
    cudaEventCreateWithFlags(&eRed,  cudaEventDisableTiming);
    cudaEventCreateWithFlags(&eIb,   cudaEventDisableTiming);
    cudaEventCreateWithFlags(&eG3a,  cudaEventDisableTiming);
    cudaEventCreateWithFlags(&eJoin, cudaEventDisableTiming);

    const int HR = ROWS / 2;  // 8192 rows per half

    // fork aux stream
    cudaEventRecord(eFork, 0);
    cudaStreamWaitEvent(s1, eFork, 0);

    // aux: W1/W2 conversions (only needed by G2/G3)
    {
        int n = FFD * DIMS / 8;
        conv_h_kernel<<<(n+255)/256, 256, 0, s1>>>(W1, pwh + W1_OFF, n);
        conv_h_kernel<<<(n+255)/256, 256, 0, s1>>>(W2, pwh + W2_OFF, n);
        cudaEventRecord(eW, s1);
    }
    // main: x/Wq/Wk conversions + bias pack (needed by G1)
    {
        int n;
        n = ROWS * DIMS / 8;   conv_h_kernel<<<(n+255)/256, 256>>>(x,  pxh, n);
        n = DIMS * DIMS / 8;   conv_h_kernel<<<(n+255)/256, 256>>>(Wq, pwh + WQK_OFF, n);
        n = DIMS * DIMS / 8;   conv_h_kernel<<<(n+255)/256, 256>>>(Wk, pwh + WQK_OFF + DIMS*DIMS, n);
        pack_bias_kernel<<<(DIMS+255)/256, 256>>>(bq, bk);
    }

    // G1 halves on main stream
    gemm_h<0,float><<<dim3(2*DIMS/128, 32), 256, SMEM>>>(pxh, pwh + WQK_OFF, pbr, pqk, 2*DIMS, DIMS, 0);
    cudaEventRecord(eG1a, 0);
    gemm_h<0,float><<<dim3(2*DIMS/128, 32), 256, SMEM>>>(pxh, pwh + WQK_OFF, pbr, pqk, 2*DIMS, DIMS, 32);
    cudaEventRecord(eG1b, 0);

    // aux: fft_fwd halves (h0 overlaps G1 h1)
    cudaStreamWaitEvent(s1, eG1a, 0);
    fft_fwd_kernel<<<HR, 256, 0, s1>>>(x, gq, betaq, gk, betak, 0);
    cudaEventRecord(eFa, s1);
    cudaStreamWaitEvent(s1, eG1b, 0);
    fft_fwd_kernel<<<HR, 256, 0, s1>>>(x, gq, betaq, gk, betak, HR);
    cudaEventRecord(eFb, s1);

    // main: reduce_s after both fft_fwd halves
    cudaStreamWaitEvent(0, eFa, 0);
    cudaStreamWaitEvent(0, eFb, 0);
    reduce_s_kernel<<<dim3(BATCH, 9), 256>>>();
    cudaEventRecord(eRed, 0);

    // fft_inv: h0 on main (critical), h1 on aux (overlaps G2 h0)
    fft_inv_ln_kernel<<<HR, 256>>>(x, g0, beta0, 0);
    cudaStreamWaitEvent(s1, eRed, 0);
    fft_inv_ln_kernel<<<HR, 256, 0, s1>>>(x, g0, beta0, HR);
    cudaEventRecord(eIb, s1);

    // G2 halves
    cudaStreamWaitEvent(0, eW, 0);
    gemm_h<1,__half><<<dim3(FFD/128, 32), 256, SMEM>>>(px1h, pwh + W1_OFF, b1, ph, FFD, DIMS, 0);
    cudaStreamWaitEvent(0, eIb, 0);
    gemm_h<1,__half><<<dim3(FFD/128, 32), 256, SMEM>>>(px1h, pwh + W1_OFF, b1, ph, FFD, DIMS, 32);

    // G3 halves
    gemm_h<0,float><<<dim3(DIMS/128, 32), 256, SMEM>>>(ph, pwh + W2_OFF, b2, pff, DIMS, FFD, 0);
    cudaEventRecord(eG3a, 0);
    gemm_h<0,float><<<dim3(DIMS/128, 32), 256, SMEM>>>(ph, pwh + W2_OFF, b2, pff, DIMS, FFD, 32);

    // resid: h0 on aux (overlaps G3 h1), h1 on main
    cudaStreamWaitEvent(s1, eG3a, 0);
    resid_ln_kernel<<<HR, 512, 0, s1>>>(g1, beta1, out, 0);
    cudaEventRecord(eJoin, s1);
    resid_ln_kernel<<<HR, 512>>>(g1, beta1, out, HR);

    // join aux back into main
    cudaStreamWaitEvent(0, eJoin, 0);
}

// round 9
// speedup vs baseline: 1.0181x; 1.0181x over previous
#include <cuda_runtime.h>
#include <cuda_fp16.h>
#include <math.h>
#include <stdint.h>

#define DIMS 1024
#define FFD  4096
#define BATCH 4
#define SEQ  4096
#define ROWS (BATCH*SEQ)   // 16384
#define NF   513           // rfft bins for N=1024

// ---------------- scratch (device globals; no allocation allowed) ----------------
__device__ __half g_qkh[(size_t)ROWS*2*DIMS];   // q | k packed, fp16 (G1 out)
__device__ float  g_x1 [(size_t)ROWS*DIMS];     // LN output (residual, fp32)
__device__ __half g_x1h[(size_t)ROWS*DIMS];     // fp16 copy (GEMM input)
__device__ float  g_ff [(size_t)ROWS*DIMS];
__device__ __half g_h  [(size_t)ROWS*FFD];      // FFN hidden, fp16
__device__ __half g_xh [(size_t)ROWS*DIMS];     // x in fp16
__device__ __half g_wh [(size_t)(2*DIMS*DIMS + 2*DIMS*FFD)]; // Wqk | W1 | W2 fp16
__device__ float  g_br [2*DIMS];                // bq | bk packed
__device__ float2 g_kx[(size_t)ROWS*NF];
__device__ float2 g_qf[(size_t)ROWS*NF];
__device__ float2 g_sf[BATCH*NF];

#define WQK_OFF 0
#define W1_OFF  (2*DIMS*DIMS)
#define W2_OFF  (2*DIMS*DIMS + DIMS*FFD)

// ---------------- PTX helpers ----------------
__device__ __forceinline__ uint32_t smem_u32(const void* p) {
    uint32_t a;
    asm("{ .reg .u64 t; cvta.to.shared.u64 t, %1; cvt.u32.u64 %0, t; }" : "=r"(a) : "l"(p));
    return a;
}
__device__ __forceinline__ uint32_t h2_as_u32(__half2 h) {
    union { __half2 h; uint32_t u; } cvt;
    cvt.h = h;
    return cvt.u;
}
__device__ __forceinline__ void cp16(uint32_t dst, const void* src) {
    asm volatile("cp.async.cg.shared.global [%0], [%1], 16;" :: "r"(dst), "l"(src));
}
#define CP_COMMIT() asm volatile("cp.async.commit_group;" ::: "memory")
template<int N> __device__ __forceinline__ void cp_wait() {
    asm volatile("cp.async.wait_group %0;" :: "n"(N) : "memory");
}
__device__ __forceinline__ void mma_f16(float& c0, float& c1, float& c2, float& c3,
                                        uint32_t a0, uint32_t a1, uint32_t a2, uint32_t a3,
                                        uint32_t b0, uint32_t b1) {
    asm volatile(
        "mma.sync.aligned.m16n8k16.row.col.f32.f16.f16.f32 "
        "{%0,%1,%2,%3}, {%4,%5,%6,%7}, {%8,%9}, {%0,%1,%2,%3};"
        : "+f"(c0), "+f"(c1), "+f"(c2), "+f"(c3)
        : "r"(a0), "r"(a1), "r"(a2), "r"(a3), "r"(b0), "r"(b1));
}
__device__ __forceinline__ void ldsm_x4(uint32_t& r0, uint32_t& r1, uint32_t& r2, uint32_t& r3,
                                        uint32_t addr) {
    asm volatile("ldmatrix.sync.aligned.m8n8.x4.shared.b16 {%0,%1,%2,%3}, [%4];"
                 : "=r"(r0), "=r"(r1), "=r"(r2), "=r"(r3) : "r"(addr));
}

// ---------------- fp32 -> fp16 convert pre-passes ----------------
__global__ void __launch_bounds__(256) conv_h_kernel(const float* __restrict__ src,
                                                     __half* __restrict__ dst, int n8) {
    int i = blockIdx.x * 256 + threadIdx.x;
    if (i < n8) {
        float4 a = ((const float4*)src)[2*i];
        float4 b = ((const float4*)src)[2*i+1];
        uint4 o;
        o.x = h2_as_u32(__floats2half2_rn(a.x, a.y));
        o.y = h2_as_u32(__floats2half2_rn(a.z, a.w));
        o.z = h2_as_u32(__floats2half2_rn(b.x, b.y));
        o.w = h2_as_u32(__floats2half2_rn(b.z, b.w));
        ((uint4*)dst)[i] = o;
    }
}
__global__ void pack_bias_kernel(const float* __restrict__ bq, const float* __restrict__ bk) {
    int i = blockIdx.x * 256 + threadIdx.x;
    if (i < DIMS) { g_br[i] = bq[i]; g_br[i + DIMS] = bk[i]; }
}

// ======================= mma.sync fp16 GEMM =======================
// C[M,N] = A[M,K]*B[N,K]^T + bias. A,B fp16 K-contiguous.
// 256x128x64 CTA tile, 256 threads (8 warps = 4M x 2N, warp tile 64x64),
// 4-stage cp.async pipeline, single sync per ktile, padded row stride 144 B.
#define BK 64
#define ROWB 144
#define A_TILE_BYTES (256*ROWB)                   // 36864
#define B_TILE_BYTES (128*ROWB)                   // 18432
#define STAGE_BYTES (A_TILE_BYTES + B_TILE_BYTES) // 55296
#define NSTAGE 4

template<int RELU, typename CT>
__global__ void __launch_bounds__(256, 1)
gemm_h(const __half* __restrict__ A, const __half* __restrict__ B,
       const float* __restrict__ bias, CT* __restrict__ C,
       int N, int K)
{
    extern __shared__ char smem[];
    const int tid = threadIdx.x;
    const int warp = tid >> 5;
    const int lane = tid & 31;
    const int wm = warp >> 1;
    const int wn = warp & 1;
    const int lr = lane >> 2;
    const int lc = lane & 3;

    const __half* Ab = A + (size_t)blockIdx.y * 256 * K;
    const __half* Bb = B + (size_t)blockIdx.x * 128 * K;

    const uint32_t sbase = smem_u32(smem);
    const int ktiles = K / BK;

    uint32_t aoff[4];
    {
        const int l7 = lane & 7;
        const int rsel = (lane >> 3) & 1;
        const int csel = lane >> 4;
        #pragma unroll
        for (int mt = 0; mt < 4; mt++) {
            int r = wm * 64 + mt * 16 + l7 + rsel * 8;
            aoff[mt] = (uint32_t)(r * ROWB + csel * 16);
        }
    }
    uint32_t boff[4];
    {
        const int l7 = lane & 7;
        const int csel = (lane >> 3) & 1;
        const int rsel = lane >> 4;
        #pragma unroll
        for (int pr = 0; pr < 4; pr++) {
            int r = wn * 64 + pr * 16 + rsel * 8 + l7;
            boff[pr] = (uint32_t)(r * ROWB + csel * 16);
        }
    }

    auto load_stage = [&](int stage, int kt) {
        const int k0 = kt * BK;
        const uint32_t sA = sbase + stage * STAGE_BYTES;
        const uint32_t sB = sA + A_TILE_BYTES;
        #pragma unroll
        for (int i = 0; i < 8; i++) {
            int g = i * 256 + tid;
            int r = g >> 3, c = g & 7;
            cp16(sA + r * ROWB + c * 16, Ab + (size_t)r * K + k0 + c * 8);
        }
        #pragma unroll
        for (int i = 0; i < 4; i++) {
            int g = i * 256 + tid;
            int r = g >> 3, c = g & 7;
            cp16(sB + r * ROWB + c * 16, Bb + (size_t)r * K + k0 + c * 8);
        }
    };

    load_stage(0, 0); CP_COMMIT();
    load_stage(1, 1); CP_COMMIT();
    load_stage(2, 2); CP_COMMIT();

    float acc[4][8][4];
    #pragma unroll
    for (int i = 0; i < 4; i++)
        #pragma unroll
        for (int j = 0; j < 8; j++)
            #pragma unroll
            for (int r = 0; r < 4; r++) acc[i][j][r] = 0.f;

    for (int it = 0; it < ktiles; it++) {
        cp_wait<NSTAGE - 2>();
        __syncthreads();   // orders prior iter's reads before this iter's prefetch writes

        const uint32_t sA = sbase + (it % NSTAGE) * STAGE_BYTES;
        const uint32_t sB = sA + A_TILE_BYTES;

        const int nt3 = it + NSTAGE - 1;
        if (nt3 < ktiles) load_stage(nt3 % NSTAGE, nt3);
        CP_COMMIT();

        #pragma unroll
        for (int ks = 0; ks < 4; ks++) {
            const uint32_t kb = ks * 32;
            uint32_t a[4][4], b[8][2];
            #pragma unroll
            for (int mt = 0; mt < 4; mt++)
                ldsm_x4(a[mt][0], a[mt][1], a[mt][2], a[mt][3], sA + aoff[mt] + kb);
            #pragma unroll
            for (int pr = 0; pr < 4; pr++)
                ldsm_x4(b[2*pr][0], b[2*pr][1], b[2*pr+1][0], b[2*pr+1][1],
                        sB + boff[pr] + kb);
            #pragma unroll
            for (int mt = 0; mt < 4; mt++)
                #pragma unroll
                for (int nt = 0; nt < 8; nt++)
                    mma_f16(acc[mt][nt][0], acc[mt][nt][1],
                            acc[mt][nt][2], acc[mt][nt][3],
                            a[mt][0], a[mt][1], a[mt][2], a[mt][3],
                            b[nt][0], b[nt][1]);
        }
    }

    // epilogue
    const int crow0 = blockIdx.y * 256 + wm * 64;
    const int ccol0 = blockIdx.x * 128 + wn * 64;
    float bb0[8], bb1[8];
    #pragma unroll
    for (int nt = 0; nt < 8; nt++) {
        bb0[nt] = __ldg(bias + ccol0 + nt * 8 + lc * 2);
        bb1[nt] = __ldg(bias + ccol0 + nt * 8 + lc * 2 + 1);
    }
    #pragma unroll
    for (int mt = 0; mt < 4; mt++) {
        #pragma unroll
        for (int nt = 0; nt < 8; nt++) {
            const int r0 = crow0 + mt * 16 + lr;
            const int c0 = ccol0 + nt * 8 + lc * 2;
            float v0 = acc[mt][nt][0] + bb0[nt];
            float v1 = acc[mt][nt][1] + bb1[nt];
            float v2 = acc[mt][nt][2] + bb0[nt];
            float v3 = acc[mt][nt][3] + bb1[nt];
            if (RELU) {
                v0 = fmaxf(v0, 0.f); v1 = fmaxf(v1, 0.f);
                v2 = fmaxf(v2, 0.f); v3 = fmaxf(v3, 0.f);
            }
            if (sizeof(CT) == 2) {
                *(__half2*)((__half*)C + (size_t)r0 * N + c0)       = __floats2half2_rn(v0, v1);
                *(__half2*)((__half*)C + (size_t)(r0 + 8) * N + c0) = __floats2half2_rn(v2, v3);
            } else {
                *(float2*)((float*)C + (size_t)r0 * N + c0)       = make_float2(v0, v1);
                *(float2*)((float*)C + (size_t)(r0 + 8) * N + c0) = make_float2(v2, v3);
            }
        }
    }
}

// ---------------- FFT path helpers ----------------
__device__ __forceinline__ float2 cmulf(float2 a, float2 b) {
    return make_float2(a.x*b.x - a.y*b.y, a.x*b.y + a.y*b.x);
}
#define F(i) ((i) ^ ((((i) >> 5) & 7) << 2))

__device__ __forceinline__ float2 block_sum2_256(float2 v, volatile float2* red) {
    int t = threadIdx.x;
    #pragma unroll
    for (int o = 16; o; o >>= 1) {
        v.x += __shfl_xor_sync(0xffffffffu, v.x, o);
        v.y += __shfl_xor_sync(0xffffffffu, v.y, o);
    }
    if ((t & 31) == 0) { red[t >> 5].x = v.x; red[t >> 5].y = v.y; }
    __syncthreads();
    if (t == 0) {
        float2 s = make_float2(0.f, 0.f);
        #pragma unroll
        for (int i = 0; i < 8; i++) { s.x += red[i].x; s.y += red[i].y; }
        red[0].x = s.x; red[0].y = s.y;
    }
    __syncthreads();
    float2 r = make_float2(red[0].x, red[0].y);
    __syncthreads();
    return r;
}

// 1024-pt radix-4 Stockham FFT (forward), 256 threads, 5 stages. Result in bufB.
__device__ __forceinline__ void fft1024_r4(float2* bufA, float2* bufB,
                                           const float2* tw, int v) {
    float2* src = bufA; float2* dst = bufB;
    #pragma unroll
    for (int st = 0; st < 5; st++) {
        const int ls = 2 * st;
        const int s = 1 << ls;
        const int idx = v & ~(s - 1);
        float2 w1 = tw[idx];
        float2 w2 = tw[2*idx];
        float2 w3 = tw[3*idx];
        float2 a = src[F(v)];
        float2 b = src[F(v + 256)];
        float2 c = src[F(v + 512)];
        float2 d = src[F(v + 768)];
        float2 apc = make_float2(a.x + c.x, a.y + c.y);
        float2 amc = make_float2(a.x - c.x, a.y - c.y);
        float2 bpd = make_float2(b.x + d.x, b.y + d.y);
        float2 jbmd = make_float2(-(b.y - d.y), b.x - d.x);
        const int bo = v + 3 * idx;
        dst[F(bo)]         = make_float2(apc.x + bpd.x, apc.y + bpd.y);
        dst[F(bo + s)]     = cmulf(w1, make_float2(amc.x - jbmd.x, amc.y - jbmd.y));
        dst[F(bo + 2*s)]   = cmulf(w2, make_float2(apc.x - bpd.x, apc.y - bpd.y));
        dst[F(bo + 3*s)]   = cmulf(w3, make_float2(amc.x + jbmd.x, amc.y + jbmd.y));
        __syncthreads();
        float2* tmp = src; src = dst; dst = tmp;
    }
}

// ---------------- forward FFTs: LN(q), LN(k); Kx = Xf*Kf; Qf ----------------
__global__ void __launch_bounds__(256) fft_fwd_kernel(
    const float* __restrict__ x,
    const float* __restrict__ gq, const float* __restrict__ betaq,
    const float* __restrict__ gk, const float* __restrict__ betak)
{
    const int row = blockIdx.x;
    const int t = threadIdx.x;
    __shared__ float2 tw[768];
    __shared__ float2 bufA[1024];
    __shared__ float2 bufB[1024];
    __shared__ float2 red2[8];

    #pragma unroll
    for (int j = 0; j < 3; j++) {
        int i = t + 256 * j;
        float s_, c_;
        sincospif((float)i * (1.0f/512.0f), &s_, &c_);
        tw[i] = make_float2(c_, -s_);
    }

    const float*  xr = x     + (size_t)row * DIMS;
    const __half* qr = g_qkh + (size_t)row * 2 * DIMS;
    const __half* kr = qr + DIMS;
    float xv[4], qv[4], kv[4];
    #pragma unroll
    for (int i = 0; i < 4; i++) {
        int e = t + 256 * i;
        xv[i] = xr[e];
        qv[i] = __half2float(qr[e]);
        kv[i] = __half2float(kr[e]);
    }

    const float invN = 1.0f / 1024.0f;
    float2 s1 = make_float2(0.f, 0.f), s2 = make_float2(0.f, 0.f);
    #pragma unroll
    for (int i = 0; i < 4; i++) {
        s1.x += qv[i]; s1.y += kv[i];
        s2.x += qv[i]*qv[i]; s2.y += kv[i]*kv[i];
    }
    s1 = block_sum2_256(s1, red2);
    s2 = block_sum2_256(s2, red2);
    float mq = s1.x * invN, vq = s2.x * invN - mq*mq;
    float rq = rsqrtf(vq + 1e-5f);
    float mk = s1.y * invN, vk = s2.y * invN - mk*mk;
    float rk = rsqrtf(vk + 1e-5f);

    float qn[4], kn[4];
    #pragma unroll
    for (int i = 0; i < 4; i++) {
        int e = t + 256 * i;
        qn[i] = (qv[i] - mq) * rq * gq[e] + betaq[e];
        kn[i] = (kv[i] - mk) * rk * gk[e] + betak[e];
    }

    #pragma unroll
    for (int i = 0; i < 4; i++) bufA[F(t + 256*i)] = make_float2(xv[i], kn[i]);
    __syncthreads();
    fft1024_r4(bufA, bufB, tw, t);

    {
        #pragma unroll
        for (int jj = 0; jj < 2; jj++) {
            int j = t + 256 * jj;
            float2 z  = bufB[F(j)];
            float2 zn = bufB[F((1024 - j) & 1023)];
            float2 xf = make_float2(0.5f*(z.x + zn.x), 0.5f*(z.y - zn.y));
            float2 df = make_float2(z.x - zn.x, z.y + zn.y);
            float2 kf = make_float2(0.5f*df.y, -0.5f*df.x);
            g_kx[(size_t)row*NF + j] = cmulf(xf, kf);
        }
        if (t == 0) {
            float2 z5 = bufB[F(512)];
            g_kx[(size_t)row*NF + 512] = make_float2(z5.x * z5.y, 0.f);
        }
    }
    #pragma unroll
    for (int i = 0; i < 4; i++) bufA[F(t + 256*i)] = make_float2(qn[i], 0.f);
    __syncthreads();
    fft1024_r4(bufA, bufB, tw, t);

    #pragma unroll
    for (int jj = 0; jj < 2; jj++) {
        int j = t + 256 * jj;
        g_qf[(size_t)row*NF + j] = bufB[F(j)];
    }
    if (t == 0) g_qf[(size_t)row*NF + 512] = bufB[F(512)];
}

// ---------------- reduce S_freq[b] = sum_s Kx[b,s]  (coalesced) ----------------
__global__ void __launch_bounds__(256) reduce_s_kernel() {
    const int b  = blockIdx.x;          // batch
    const int jc = blockIdx.y;          // 0..8  (64 bins each)
    const int t  = threadIdx.x;
    const int jl = t & 63;
    const int sl = t >> 6;              // 0..3
    const int j  = jc * 64 + jl;
    float2 acc = make_float2(0.f, 0.f);
    if (j < NF) {
        const float2* p = g_kx + (size_t)b * SEQ * NF + j;
        for (int s = sl; s < SEQ; s += 4) {
            float2 v = p[(size_t)s * NF];
            acc.x += v.x; acc.y += v.y;
        }
    }
    __shared__ float2 red[256];
    red[t] = acc;
    __syncthreads();
    if (t < 128) { red[t].x += red[t+128].x; red[t].y += red[t+128].y; }
    __syncthreads();
    if (t < 64) {
        red[t].x += red[t+64].x; red[t].y += red[t+64].y;
        if (j < NF) g_sf[b * NF + j] = red[t];
    }
}

// ---------------- inverse FFT of mixF = Kx + S*conj(Qf); LN(x + mix) ----------------
__global__ void __launch_bounds__(256) fft_inv_ln_kernel(
    const float* __restrict__ x,
    const float* __restrict__ g0, const float* __restrict__ beta0)
{
    const int row = blockIdx.x;
    const int b = row >> 12;
    const int t = threadIdx.x;
    __shared__ float2 tw[768];
    __shared__ float2 bufA[1024];
    __shared__ float2 bufB[1024];
    __shared__ float2 red2[8];

    #pragma unroll
    for (int j = 0; j < 3; j++) {
        int i = t + 256 * j;
        float s_, c_;
        sincospif((float)i * (1.0f/512.0f), &s_, &c_);
        tw[i] = make_float2(c_, -s_);
    }

    #pragma unroll
    for (int jj = 0; jj < 2; jj++) {
        int j = t + 256 * jj;
        float2 kx = g_kx[(size_t)row*NF + j];
        float2 sf = g_sf[b*NF + j];
        float2 qf = g_qf[(size_t)row*NF + j];
        float2 qc = make_float2(qf.x, -qf.y);
        float2 p  = cmulf(sf, qc);
        float2 mv = make_float2(kx.x + p.x, kx.y + p.y);
        bufA[F(j)] = make_float2(mv.x, -mv.y);
        if (j > 0) bufA[F(1024 - j)] = mv;
    }
    if (t == 0) {
        float2 kx5 = g_kx[(size_t)row*NF + 512];
        float2 sf5 = g_sf[b*NF + 512];
        float2 qf5 = g_qf[(size_t)row*NF + 512];
        float2 qc5 = make_float2(qf5.x, -qf5.y);
        float2 p5  = cmulf(sf5, qc5);
        bufA[F(512)] = make_float2(kx5.x + p5.x, -(kx5.y + p5.y));
    }
    __syncthreads();
    fft1024_r4(bufA, bufB, tw, t);

    const float invN = 1.0f / 1024.0f;
    const float* xr = x + (size_t)row * DIMS;
    float y[4];
    float2 s12 = make_float2(0.f, 0.f);
    #pragma unroll
    for (int i = 0; i < 4; i++) {
        int e = t + 256 * i;
        y[i] = xr[e] + bufB[F(e)].x * invN;
        s12.x += y[i];
        s12.y += y[i] * y[i];
    }
    s12 = block_sum2_256(s12, red2);
    float m = s12.x * invN, v = s12.y * invN - m*m;
    float r = rsqrtf(v + 1e-5f);
    float*  o  = g_x1  + (size_t)row * DIMS;
    __half* oh = g_x1h + (size_t)row * DIMS;
    #pragma unroll
    for (int i = 0; i < 4; i++) {
        int e = t + 256 * i;
        float ov = (y[i] - m) * r * g0[e] + beta0[e];
        o[e]  = ov;
        oh[e] = __float2half_rn(ov);
    }
}

// ---------------- out = LN(x1 + ff) ----------------
__device__ __forceinline__ float block_sum512(float v, volatile float* red) {
    int t = threadIdx.x;
    #pragma unroll
    for (int o = 16; o; o >>= 1) v += __shfl_xor_sync(0xffffffffu, v, o);
    if ((t & 31) == 0) red[t >> 5] = v;
    __syncthreads();
    if (t == 0) {
        float s = 0.f;
        #pragma unroll
        for (int i = 0; i < 16; i++) s += red[i];
        red[0] = s;
    }
    __syncthreads();
    float r = red[0];
    __syncthreads();
    return r;
}

__global__ void __launch_bounds__(512) resid_ln_kernel(
    const float* __restrict__ g1v, const float* __restrict__ beta1,
    float* __restrict__ out)
{
    const int row = blockIdx.x;
    const int t = threadIdx.x;
    __shared__ float red[16];
    const float* a = g_x1 + (size_t)row * DIMS;
    const float* f = g_ff + (size_t)row * DIMS;
    float y0 = a[t]     + f[t];
    float y1 = a[t+512] + f[t+512];
    const float invN = 1.0f / 1024.0f;
    float s  = block_sum512(y0 + y1, red);
    float ss = block_sum512(y0*y0 + y1*y1, red);
    float m = s * invN, v = ss * invN - m*m;
    float r = rsqrtf(v + 1e-5f);
    float* o = out + (size_t)row * DIMS;
    o[t]     = (y0 - m) * r * g1v[t]     + beta1[t];
    o[t+512] = (y1 - m) * r * g1v[t+512] + beta1[t+512];
}

// ---------------- launch ----------------
extern "C" void kernel_launch(void* const* d_in, const int* in_sizes, int n_in,
                              void* d_out, int out_size)
{
    const float* x     = (const float*)d_in[0];
    const float* Wq    = (const float*)d_in[1];
    const float* bq    = (const float*)d_in[2];
    const float* gq    = (const float*)d_in[3];
    const float* betaq = (const float*)d_in[4];
    const float* Wk    = (const float*)d_in[5];
    const float* bk    = (const float*)d_in[6];
    const float* gk    = (const float*)d_in[7];
    const float* betak = (const float*)d_in[8];
    const float* g0    = (const float*)d_in[9];
    const float* beta0 = (const float*)d_in[10];
    const float* W1    = (const float*)d_in[11];
    const float* b1    = (const float*)d_in[12];
    const float* W2    = (const float*)d_in[13];
    const float* b2    = (const float*)d_in[14];
    const float* g1    = (const float*)d_in[15];
    const float* beta1 = (const float*)d_in[16];
    float* out = (float*)d_out;

    float *pff, *pbr;
    __half *pqkh, *px1h, *ph, *pxh, *pwh;
    cudaGetSymbolAddress((void**)&pqkh, g_qkh);
    cudaGetSymbolAddress((void**)&px1h, g_x1h);
    cudaGetSymbolAddress((void**)&ph,   g_h);
    cudaGetSymbolAddress((void**)&pff,  g_ff);
    cudaGetSymbolAddress((void**)&pxh,  g_xh);
    cudaGetSymbolAddress((void**)&pwh,  g_wh);
    cudaGetSymbolAddress((void**)&pbr,  g_br);

    const int SMEM = NSTAGE * STAGE_BYTES;  // 221184 B
    cudaFuncSetAttribute(gemm_h<0,float>,  cudaFuncAttributeMaxDynamicSharedMemorySize, SMEM);
    cudaFuncSetAttribute(gemm_h<0,__half>, cudaFuncAttributeMaxDynamicSharedMemorySize, SMEM);
    cudaFuncSetAttribute(gemm_h<1,__half>, cudaFuncAttributeMaxDynamicSharedMemorySize, SMEM);

    // fp16 conversions (rn), pack Wq|Wk and bq|bk
    {
        int n;
        n = ROWS * DIMS / 8;   conv_h_kernel<<<(n+255)/256, 256>>>(x,  pxh, n);
        n = DIMS * DIMS / 8;   conv_h_kernel<<<(n+255)/256, 256>>>(Wq, pwh + WQK_OFF, n);
        n = DIMS * DIMS / 8;   conv_h_kernel<<<(n+255)/256, 256>>>(Wk, pwh + WQK_OFF + DIMS*DIMS, n);
        n = FFD * DIMS / 8;    conv_h_kernel<<<(n+255)/256, 256>>>(W1, pwh + W1_OFF, n);
        n = DIMS * FFD / 8;    conv_h_kernel<<<(n+255)/256, 256>>>(W2, pwh + W2_OFF, n);
        pack_bias_kernel<<<(DIMS+255)/256, 256>>>(bq, bk);
    }

    // [q|k] = x @ [Wq|Wk]^T + [bq|bk]   (fused, N=2048, fp16 out)
    gemm_h<0,__half><<<dim3(2*DIMS/128, ROWS/256), 256, SMEM>>>(pxh, pwh + WQK_OFF, pbr, pqkh, 2*DIMS, DIMS);
    // LN(q), LN(k), forward FFTs, Kx, Qf  (radix-4)
    fft_fwd_kernel<<<ROWS, 256>>>(x, gq, betaq, gk, betak);
    // S = sum_s Kx (freq domain, coalesced)
    reduce_s_kernel<<<dim3(BATCH, 9), 256>>>();
    // mix = irfft(Kx + S*conj(Qf)); x1 = LN(x + mix) (+fp16 copy)
    fft_inv_ln_kernel<<<ROWS, 256>>>(x, g0, beta0);
    // h = relu(x1 @ W1^T + b1) -> fp16
    gemm_h<1,__half><<<dim3(FFD/128, ROWS/256), 256, SMEM>>>(px1h, pwh + W1_OFF, b1, ph, FFD, DIMS);
    // ff = h @ W2^T + b2
    gemm_h<0,float><<<dim3(DIMS/128, ROWS/256), 256, SMEM>>>(ph, pwh + W2_OFF, b2, pff, DIMS, FFD);
    // out = LN(x1 + ff)
    resid_ln_kernel<<<ROWS, 512>>>(g1, beta1, out);
}

// round 10
// speedup vs baseline: 1.0627x; 1.0439x over previous
#include <cuda_runtime.h>
#include <cuda_fp16.h>
#include <math.h>
#include <stdint.h>

#define DIMS 1024
#define FFD  4096
#define BATCH 4
#define SEQ  4096
#define ROWS (BATCH*SEQ)   // 16384
#define NF   513           // rfft bins for N=1024

// ---------------- scratch (device globals; no allocation allowed) ----------------
__device__ __half g_qkh[(size_t)ROWS*2*DIMS];   // q | k packed, fp16 (G1 out)
__device__ float  g_x1 [(size_t)ROWS*DIMS];     // LN output (residual, fp32)
__device__ __half g_x1h[(size_t)ROWS*DIMS];     // fp16 copy (GEMM input)
__device__ float  g_ff [(size_t)ROWS*DIMS];
__device__ __half g_h  [(size_t)ROWS*FFD];      // FFN hidden, fp16
__device__ __half g_xh [(size_t)ROWS*DIMS];     // x in fp16
__device__ __half g_wh [(size_t)(2*DIMS*DIMS + 2*DIMS*FFD)]; // Wqk | W1 | W2 fp16
__device__ float  g_br [2*DIMS];                // bq | bk packed
__device__ float2 g_kx[(size_t)ROWS*NF];
__device__ float2 g_qf[(size_t)ROWS*NF];
__device__ float2 g_sf[BATCH*NF];

#define WQK_OFF 0
#define W1_OFF  (2*DIMS*DIMS)
#define W2_OFF  (2*DIMS*DIMS + DIMS*FFD)

// ---------------- PTX helpers ----------------
__device__ __forceinline__ uint32_t smem_u32(const void* p) {
    uint32_t a;
    asm("{ .reg .u64 t; cvta.to.shared.u64 t, %1; cvt.u32.u64 %0, t; }" : "=r"(a) : "l"(p));
    return a;
}
__device__ __forceinline__ uint32_t h2_as_u32(__half2 h) {
    union { __half2 h; uint32_t u; } cvt;
    cvt.h = h;
    return cvt.u;
}
__device__ __forceinline__ void cp16(uint32_t dst, const void* src) {
    asm volatile("cp.async.cg.shared.global [%0], [%1], 16;" :: "r"(dst), "l"(src));
}
#define CP_COMMIT() asm volatile("cp.async.commit_group;" ::: "memory")
template<int N> __device__ __forceinline__ void cp_wait() {
    asm volatile("cp.async.wait_group %0;" :: "n"(N) : "memory");
}
__device__ __forceinline__ void mma_f16(float& c0, float& c1, float& c2, float& c3,
                                        uint32_t a0, uint32_t a1, uint32_t a2, uint32_t a3,
                                        uint32_t b0, uint32_t b1) {
    asm volatile(
        "mma.sync.aligned.m16n8k16.row.col.f32.f16.f16.f32 "
        "{%0,%1,%2,%3}, {%4,%5,%6,%7}, {%8,%9}, {%0,%1,%2,%3};"
        : "+f"(c0), "+f"(c1), "+f"(c2), "+f"(c3)
        : "r"(a0), "r"(a1), "r"(a2), "r"(a3), "r"(b0), "r"(b1));
}
__device__ __forceinline__ void ldsm_x4(uint32_t& r0, uint32_t& r1, uint32_t& r2, uint32_t& r3,
                                        uint32_t addr) {
    asm volatile("ldmatrix.sync.aligned.m8n8.x4.shared.b16 {%0,%1,%2,%3}, [%4];"
                 : "=r"(r0), "=r"(r1), "=r"(r2), "=r"(r3) : "r"(addr));
}

// ---------------- fp32 -> fp16 convert pre-passes ----------------
__global__ void __launch_bounds__(256) conv_h_kernel(const float* __restrict__ src,
                                                     __half* __restrict__ dst, int n8) {
    int i = blockIdx.x * 256 + threadIdx.x;
    if (i < n8) {
        float4 a = ((const float4*)src)[2*i];
        float4 b = ((const float4*)src)[2*i+1];
        uint4 o;
        o.x = h2_as_u32(__floats2half2_rn(a.x, a.y));
        o.y = h2_as_u32(__floats2half2_rn(a.z, a.w));
        o.z = h2_as_u32(__floats2half2_rn(b.x, b.y));
        o.w = h2_as_u32(__floats2half2_rn(b.z, b.w));
        ((uint4*)dst)[i] = o;
    }
}
__global__ void pack_bias_kernel(const float* __restrict__ bq, const float* __restrict__ bk) {
    int i = blockIdx.x * 256 + threadIdx.x;
    if (i < DIMS) { g_br[i] = bq[i]; g_br[i + DIMS] = bk[i]; }
}

// ======================= mma.sync fp16 GEMM =======================
#define BK 64
#define ROWB 144
#define A_TILE_BYTES (256*ROWB)
#define B_TILE_BYTES (128*ROWB)
#define STAGE_BYTES (A_TILE_BYTES + B_TILE_BYTES)
#define NSTAGE 4

template<int RELU, typename CT>
__global__ void __launch_bounds__(256, 1)
gemm_h(const __half* __restrict__ A, const __half* __restrict__ B,
       const float* __restrict__ bias, CT* __restrict__ C,
       int N, int K)
{
    extern __shared__ char smem[];
    const int tid = threadIdx.x;
    const int warp = tid >> 5;
    const int lane = tid & 31;
    const int wm = warp >> 1;
    const int wn = warp & 1;
    const int lr = lane >> 2;
    const int lc = lane & 3;

    const __half* Ab = A + (size_t)blockIdx.y * 256 * K;
    const __half* Bb = B + (size_t)blockIdx.x * 128 * K;

    const uint32_t sbase = smem_u32(smem);
    const int ktiles = K / BK;

    uint32_t aoff[4];
    {
        const int l7 = lane & 7;
        const int rsel = (lane >> 3) & 1;
        const int csel = lane >> 4;
        #pragma unroll
        for (int mt = 0; mt < 4; mt++) {
            int r = wm * 64 + mt * 16 + l7 + rsel * 8;
            aoff[mt] = (uint32_t)(r * ROWB + csel * 16);
        }
    }
    uint32_t boff[4];
    {
        const int l7 = lane & 7;
        const int csel = (lane >> 3) & 1;
        const int rsel = lane >> 4;
        #pragma unroll
        for (int pr = 0; pr < 4; pr++) {
            int r = wn * 64 + pr * 16 + rsel * 8 + l7;
            boff[pr] = (uint32_t)(r * ROWB + csel * 16);
        }
    }

    auto load_stage = [&](int stage, int kt) {
        const int k0 = kt * BK;
        const uint32_t sA = sbase + stage * STAGE_BYTES;
        const uint32_t sB = sA + A_TILE_BYTES;
        #pragma unroll
        for (int i = 0; i < 8; i++) {
            int g = i * 256 + tid;
            int r = g >> 3, c = g & 7;
            cp16(sA + r * ROWB + c * 16, Ab + (size_t)r * K + k0 + c * 8);
        }
        #pragma unroll
        for (int i = 0; i < 4; i++) {
            int g = i * 256 + tid;
            int r = g >> 3, c = g & 7;
            cp16(sB + r * ROWB + c * 16, Bb + (size_t)r * K + k0 + c * 8);
        }
    };

    load_stage(0, 0); CP_COMMIT();
    load_stage(1, 1); CP_COMMIT();
    load_stage(2, 2); CP_COMMIT();

    float acc[4][8][4];
    #pragma unroll
    for (int i = 0; i < 4; i++)
        #pragma unroll
        for (int j = 0; j < 8; j++)
            #pragma unroll
            for (int r = 0; r < 4; r++) acc[i][j][r] = 0.f;

    for (int it = 0; it < ktiles; it++) {
        cp_wait<NSTAGE - 2>();
        __syncthreads();

        const uint32_t sA = sbase + (it % NSTAGE) * STAGE_BYTES;
        const uint32_t sB = sA + A_TILE_BYTES;

        const int nt3 = it + NSTAGE - 1;
        if (nt3 < ktiles) load_stage(nt3 % NSTAGE, nt3);
        CP_COMMIT();

        #pragma unroll
        for (int ks = 0; ks < 4; ks++) {
            const uint32_t kb = ks * 32;
            uint32_t a[4][4], b[8][2];
            #pragma unroll
            for (int mt = 0; mt < 4; mt++)
                ldsm_x4(a[mt][0], a[mt][1], a[mt][2], a[mt][3], sA + aoff[mt] + kb);
            #pragma unroll
            for (int pr = 0; pr < 4; pr++)
                ldsm_x4(b[2*pr][0], b[2*pr][1], b[2*pr+1][0], b[2*pr+1][1],
                        sB + boff[pr] + kb);
            #pragma unroll
            for (int mt = 0; mt < 4; mt++)
                #pragma unroll
                for (int nt = 0; nt < 8; nt++)
                    mma_f16(acc[mt][nt][0], acc[mt][nt][1],
                            acc[mt][nt][2], acc[mt][nt][3],
                            a[mt][0], a[mt][1], a[mt][2], a[mt][3],
                            b[nt][0], b[nt][1]);
        }
    }

    const int crow0 = blockIdx.y * 256 + wm * 64;
    const int ccol0 = blockIdx.x * 128 + wn * 64;
    float bb0[8], bb1[8];
    #pragma unroll
    for (int nt = 0; nt < 8; nt++) {
        bb0[nt] = __ldg(bias + ccol0 + nt * 8 + lc * 2);
        bb1[nt] = __ldg(bias + ccol0 + nt * 8 + lc * 2 + 1);
    }
    #pragma unroll
    for (int mt = 0; mt < 4; mt++) {
        #pragma unroll
        for (int nt = 0; nt < 8; nt++) {
            const int r0 = crow0 + mt * 16 + lr;
            const int c0 = ccol0 + nt * 8 + lc * 2;
            float v0 = acc[mt][nt][0] + bb0[nt];
            float v1 = acc[mt][nt][1] + bb1[nt];
            float v2 = acc[mt][nt][2] + bb0[nt];
            float v3 = acc[mt][nt][3] + bb1[nt];
            if (RELU) {
                v0 = fmaxf(v0, 0.f); v1 = fmaxf(v1, 0.f);
                v2 = fmaxf(v2, 0.f); v3 = fmaxf(v3, 0.f);
            }
            if (sizeof(CT) == 2) {
                *(__half2*)((__half*)C + (size_t)r0 * N + c0)       = __floats2half2_rn(v0, v1);
                *(__half2*)((__half*)C + (size_t)(r0 + 8) * N + c0) = __floats2half2_rn(v2, v3);
            } else {
                *(float2*)((float*)C + (size_t)r0 * N + c0)       = make_float2(v0, v1);
                *(float2*)((float*)C + (size_t)(r0 + 8) * N + c0) = make_float2(v2, v3);
            }
        }
    }
}

// ---------------- FFT path helpers ----------------
__device__ __forceinline__ float2 cmulf(float2 a, float2 b) {
    return make_float2(a.x*b.x - a.y*b.y, a.x*b.y + a.y*b.x);
}
#define F(i) ((i) ^ ((((i) >> 5) & 7) << 2))

__device__ __forceinline__ float2 block_sum2_256(float2 v, volatile float2* red) {
    int t = threadIdx.x;
    #pragma unroll
    for (int o = 16; o; o >>= 1) {
        v.x += __shfl_xor_sync(0xffffffffu, v.x, o);
        v.y += __shfl_xor_sync(0xffffffffu, v.y, o);
    }
    if ((t & 31) == 0) { red[t >> 5].x = v.x; red[t >> 5].y = v.y; }
    __syncthreads();
    if (t == 0) {
        float2 s = make_float2(0.f, 0.f);
        #pragma unroll
        for (int i = 0; i < 8; i++) { s.x += red[i].x; s.y += red[i].y; }
        red[0].x = s.x; red[0].y = s.y;
    }
    __syncthreads();
    float2 r = make_float2(red[0].x, red[0].y);
    __syncthreads();
    return r;
}

// 1024-pt radix-4 Stockham FFT (forward), 256 threads, 5 stages. Result in bufB.
__device__ __forceinline__ void fft1024_r4(float2* bufA, float2* bufB,
                                           const float2* tw, int v) {
    float2* src = bufA; float2* dst = bufB;
    #pragma unroll
    for (int st = 0; st < 5; st++) {
        const int ls = 2 * st;
        const int s = 1 << ls;
        const int idx = v & ~(s - 1);
        float2 w1 = tw[idx];
        float2 w2 = tw[2*idx];
        float2 w3 = tw[3*idx];
        float2 a = src[F(v)];
        float2 b = src[F(v + 256)];
        float2 c = src[F(v + 512)];
        float2 d = src[F(v + 768)];
        float2 apc = make_float2(a.x + c.x, a.y + c.y);
        float2 amc = make_float2(a.x - c.x, a.y - c.y);
        float2 bpd = make_float2(b.x + d.x, b.y + d.y);
        float2 jbmd = make_float2(-(b.y - d.y), b.x - d.x);
        const int bo = v + 3 * idx;
        dst[F(bo)]         = make_float2(apc.x + bpd.x, apc.y + bpd.y);
        dst[F(bo + s)]     = cmulf(w1, make_float2(amc.x - jbmd.x, amc.y - jbmd.y));
        dst[F(bo + 2*s)]   = cmulf(w2, make_float2(apc.x - bpd.x, apc.y - bpd.y));
        dst[F(bo + 3*s)]   = cmulf(w3, make_float2(amc.x + jbmd.x, amc.y + jbmd.y));
        __syncthreads();
        float2* tmp = src; src = dst; dst = tmp;
    }
}

// ---------------- forward: LN(q,k) x2 rows; 3 FFTs per 2 rows ----------------
__global__ void __launch_bounds__(256) fft_fwd_kernel(
    const float* __restrict__ x,
    const float* __restrict__ gq, const float* __restrict__ betaq,
    const float* __restrict__ gk, const float* __restrict__ betak)
{
    const int row0 = blockIdx.x * 2;
    const int row1 = row0 + 1;
    const int t = threadIdx.x;
    __shared__ float2 tw[768];
    __shared__ float2 bufA[1024];
    __shared__ float2 bufB[1024];
    __shared__ float2 red2[8];

    #pragma unroll
    for (int j = 0; j < 3; j++) {
        int i = t + 256 * j;
        float s_, c_;
        sincospif((float)i * (1.0f/512.0f), &s_, &c_);
        tw[i] = make_float2(c_, -s_);
    }

    const float invN = 1.0f / 1024.0f;
    float xv[2][4], qn[2][4], kn[2][4];
    #pragma unroll
    for (int r = 0; r < 2; r++) {
        const int row = row0 + r;
        const float*  xr = x     + (size_t)row * DIMS;
        const __half* qr = g_qkh + (size_t)row * 2 * DIMS;
        const __half* kr = qr + DIMS;
        float qv[4], kv[4];
        #pragma unroll
        for (int i = 0; i < 4; i++) {
            int e = t + 256 * i;
            xv[r][i] = xr[e];
            qv[i] = __half2float(qr[e]);
            kv[i] = __half2float(kr[e]);
        }
        float2 s1 = make_float2(0.f, 0.f), s2 = make_float2(0.f, 0.f);
        #pragma unroll
        for (int i = 0; i < 4; i++) {
            s1.x += qv[i]; s1.y += kv[i];
            s2.x += qv[i]*qv[i]; s2.y += kv[i]*kv[i];
        }
        s1 = block_sum2_256(s1, red2);
        s2 = block_sum2_256(s2, red2);
        float mq = s1.x * invN, vq = s2.x * invN - mq*mq;
        float rq = rsqrtf(vq + 1e-5f);
        float mk = s1.y * invN, vk = s2.y * invN - mk*mk;
        float rk = rsqrtf(vk + 1e-5f);
        #pragma unroll
        for (int i = 0; i < 4; i++) {
            int e = t + 256 * i;
            qn[r][i] = (qv[i] - mq) * rq * gq[e] + betaq[e];
            kn[r][i] = (kv[i] - mk) * rk * gk[e] + betak[e];
        }
    }

    // FFT of x_r + i*kn_r  ->  Kx row r   (two passes)
    #pragma unroll
    for (int r = 0; r < 2; r++) {
        const int row = row0 + r;
        #pragma unroll
        for (int i = 0; i < 4; i++) bufA[F(t + 256*i)] = make_float2(xv[r][i], kn[r][i]);
        __syncthreads();
        fft1024_r4(bufA, bufB, tw, t);
        #pragma unroll
        for (int jj = 0; jj < 2; jj++) {
            int j = t + 256 * jj;
            float2 z  = bufB[F(j)];
            float2 zn = bufB[F((1024 - j) & 1023)];
            float2 xf = make_float2(0.5f*(z.x + zn.x), 0.5f*(z.y - zn.y));
            float2 df = make_float2(z.x - zn.x, z.y + zn.y);
            float2 kf = make_float2(0.5f*df.y, -0.5f*df.x);
            g_kx[(size_t)row*NF + j] = cmulf(xf, kf);
        }
        if (t == 0) {
            float2 z5 = bufB[F(512)];
            g_kx[(size_t)row*NF + 512] = make_float2(z5.x * z5.y, 0.f);
        }
        __syncthreads();
    }

    // FFT of qn0 + i*qn1  ->  Qf rows row0, row1 (even/odd split)
    #pragma unroll
    for (int i = 0; i < 4; i++) bufA[F(t + 256*i)] = make_float2(qn[0][i], qn[1][i]);
    __syncthreads();
    fft1024_r4(bufA, bufB, tw, t);
    #pragma unroll
    for (int jj = 0; jj < 2; jj++) {
        int j = t + 256 * jj;
        float2 z  = bufB[F(j)];
        float2 zn = bufB[F((1024 - j) & 1023)];
        // Q0 = (Z + conj(Zn))/2 ; Q1 = (Z - conj(Zn))/(2i)
        float2 q0 = make_float2(0.5f*(z.x + zn.x), 0.5f*(z.y - zn.y));
        float2 df = make_float2(z.x - zn.x, z.y + zn.y);
        float2 q1 = make_float2(0.5f*df.y, -0.5f*df.x);
        g_qf[(size_t)row0*NF + j] = q0;
        g_qf[(size_t)row1*NF + j] = q1;
    }
    if (t == 0) {
        float2 z5 = bufB[F(512)];
        g_qf[(size_t)row0*NF + 512] = make_float2(z5.x, 0.f);
        g_qf[(size_t)row1*NF + 512] = make_float2(z5.y, 0.f);
    }
}

// ---------------- reduce S_freq[b] = sum_s Kx[b,s]  (coalesced) ----------------
__global__ void __launch_bounds__(256) reduce_s_kernel() {
    const int b  = blockIdx.x;
    const int jc = blockIdx.y;
    const int t  = threadIdx.x;
    const int jl = t & 63;
    const int sl = t >> 6;
    const int j  = jc * 64 + jl;
    float2 acc = make_float2(0.f, 0.f);
    if (j < NF) {
        const float2* p = g_kx + (size_t)b * SEQ * NF + j;
        for (int s = sl; s < SEQ; s += 4) {
            float2 v = p[(size_t)s * NF];
            acc.x += v.x; acc.y += v.y;
        }
    }
    __shared__ float2 red[256];
    red[t] = acc;
    __syncthreads();
    if (t < 128) { red[t].x += red[t+128].x; red[t].y += red[t+128].y; }
    __syncthreads();
    if (t < 64) {
        red[t].x += red[t+64].x; red[t].y += red[t+64].y;
        if (j < NF) g_sf[b * NF + j] = red[t];
    }
}

// ---------------- inverse: 1 FFT per 2 rows; LN(x+mix) x2 ----------------
__global__ void __launch_bounds__(256) fft_inv_ln_kernel(
    const float* __restrict__ x,
    const float* __restrict__ g0, const float* __restrict__ beta0)
{
    const int row0 = blockIdx.x * 2;
    const int row1 = row0 + 1;
    const int b = row0 >> 12;   // rows are paired within a batch (SEQ even)
    const int t = threadIdx.x;
    __shared__ float2 tw[768];
    __shared__ float2 bufA[1024];
    __shared__ float2 bufB[1024];
    __shared__ float2 red2[8];

    #pragma unroll
    for (int j = 0; j < 3; j++) {
        int i = t + 256 * j;
        float s_, c_;
        sincospif((float)i * (1.0f/512.0f), &s_, &c_);
        tw[i] = make_float2(c_, -s_);
    }

    // Build conj(Z) where Z = M0 + i*M1 (Hermitian spectra of rows 0/1)
    #pragma unroll
    for (int jj = 0; jj < 2; jj++) {
        int j = t + 256 * jj;
        float2 sf = g_sf[b*NF + j];
        float2 kx0 = g_kx[(size_t)row0*NF + j];
        float2 qf0 = g_qf[(size_t)row0*NF + j];
        float2 m0 = make_float2(kx0.x + sf.x*qf0.x + sf.y*qf0.y,
                                kx0.y - sf.x*qf0.y + sf.y*qf0.x);  // kx + sf*conj(qf)
        float2 kx1 = g_kx[(size_t)row1*NF + j];
        float2 qf1 = g_qf[(size_t)row1*NF + j];
        float2 m1 = make_float2(kx1.x + sf.x*qf1.x + sf.y*qf1.y,
                                kx1.y - sf.x*qf1.y + sf.y*qf1.x);
        // bufA[j]      = conj(M0) - i*conj(M1) = (m0.x - m1.y, -m0.y - m1.x)
        bufA[F(j)] = make_float2(m0.x - m1.y, -m0.y - m1.x);
        // bufA[1024-j] = M0 - i*M1           = (m0.x + m1.y,  m0.y - m1.x)
        if (j > 0) bufA[F(1024 - j)] = make_float2(m0.x + m1.y, m0.y - m1.x);
    }
    if (t == 0) {
        float2 sf = g_sf[b*NF + 512];
        float2 kx0 = g_kx[(size_t)row0*NF + 512];
        float2 qf0 = g_qf[(size_t)row0*NF + 512];
        float m0 = kx0.x + sf.x*qf0.x;      // all real at Nyquist
        float2 kx1 = g_kx[(size_t)row1*NF + 512];
        float2 qf1 = g_qf[(size_t)row1*NF + 512];
        float m1 = kx1.x + sf.x*qf1.x;
        bufA[F(512)] = make_float2(m0, -m1);
    }
    __syncthreads();
    fft1024_r4(bufA, bufB, tw, t);
    // y0 = Re(W)/N ; y1 = -Im(W)/N

    const float invN = 1.0f / 1024.0f;
    #pragma unroll
    for (int r = 0; r < 2; r++) {
        const int row = row0 + r;
        const float* xr = x + (size_t)row * DIMS;
        float y[4];
        float2 s12 = make_float2(0.f, 0.f);
        #pragma unroll
        for (int i = 0; i < 4; i++) {
            int e = t + 256 * i;
            float2 w = bufB[F(e)];
            float mixv = (r == 0 ? w.x : -w.y) * invN;
            y[i] = xr[e] + mixv;
            s12.x += y[i];
            s12.y += y[i] * y[i];
        }
        s12 = block_sum2_256(s12, red2);
        float m = s12.x * invN, v = s12.y * invN - m*m;
        float rr = rsqrtf(v + 1e-5f);
        float*  o  = g_x1  + (size_t)row * DIMS;
        __half* oh = g_x1h + (size_t)row * DIMS;
        #pragma unroll
        for (int i = 0; i < 4; i++) {
            int e = t + 256 * i;
            float ov = (y[i] - m) * rr * g0[e] + beta0[e];
            o[e]  = ov;
            oh[e] = __float2half_rn(ov);
        }
    }
}

// ---------------- out = LN(x1 + ff) ----------------
__device__ __forceinline__ float block_sum512(float v, volatile float* red) {
    int t = threadIdx.x;
    #pragma unroll
    for (int o = 16; o; o >>= 1) v += __shfl_xor_sync(0xffffffffu, v, o);
    if ((t & 31) == 0) red[t >> 5] = v;
    __syncthreads();
    if (t == 0) {
        float s = 0.f;
        #pragma unroll
        for (int i = 0; i < 16; i++) s += red[i];
        red[0] = s;
    }
    __syncthreads();
    float r = red[0];
    __syncthreads();
    return r;
}

__global__ void __launch_bounds__(512) resid_ln_kernel(
    const float* __restrict__ g1v, const float* __restrict__ beta1,
    float* __restrict__ out)
{
    const int row = blockIdx.x;
    const int t = threadIdx.x;
    __shared__ float red[16];
    const float* a = g_x1 + (size_t)row * DIMS;
    const float* f = g_ff + (size_t)row * DIMS;
    float y0 = a[t]     + f[t];
    float y1 = a[t+512] + f[t+512];
    const float invN = 1.0f / 1024.0f;
    float s  = block_sum512(y0 + y1, red);
    float ss = block_sum512(y0*y0 + y1*y1, red);
    float m = s * invN, v = ss * invN - m*m;
    float r = rsqrtf(v + 1e-5f);
    float* o = out + (size_t)row * DIMS;
    o[t]     = (y0 - m) * r * g1v[t]     + beta1[t];
    o[t+512] = (y1 - m) * r * g1v[t+512] + beta1[t+512];
}

// ---------------- launch ----------------
extern "C" void kernel_launch(void* const* d_in, const int* in_sizes, int n_in,
                              void* d_out, int out_size)
{
    const float* x     = (const float*)d_in[0];
    const float* Wq    = (const float*)d_in[1];
    const float* bq    = (const float*)d_in[2];
    const float* gq    = (const float*)d_in[3];
    const float* betaq = (const float*)d_in[4];
    const float* Wk    = (const float*)d_in[5];
    const float* bk    = (const float*)d_in[6];
    const float* gk    = (const float*)d_in[7];
    const float* betak = (const float*)d_in[8];
    const float* g0    = (const float*)d_in[9];
    const float* beta0 = (const float*)d_in[10];
    const float* W1    = (const float*)d_in[11];
    const float* b1    = (const float*)d_in[12];
    const float* W2    = (const float*)d_in[13];
    const float* b2    = (const float*)d_in[14];
    const float* g1    = (const float*)d_in[15];
    const float* beta1 = (const float*)d_in[16];
    float* out = (float*)d_out;

    float *pff, *pbr;
    __half *pqkh, *px1h, *ph, *pxh, *pwh;
    cudaGetSymbolAddress((void**)&pqkh, g_qkh);
    cudaGetSymbolAddress((void**)&px1h, g_x1h);
    cudaGetSymbolAddress((void**)&ph,   g_h);
    cudaGetSymbolAddress((void**)&pff,  g_ff);
    cudaGetSymbolAddress((void**)&pxh,  g_xh);
    cudaGetSymbolAddress((void**)&pwh,  g_wh);
    cudaGetSymbolAddress((void**)&pbr,  g_br);

    const int SMEM = NSTAGE * STAGE_BYTES;  // 221184 B
    cudaFuncSetAttribute(gemm_h<0,float>,  cudaFuncAttributeMaxDynamicSharedMemorySize, SMEM);
    cudaFuncSetAttribute(gemm_h<0,__half>, cudaFuncAttributeMaxDynamicSharedMemorySize, SMEM);
    cudaFuncSetAttribute(gemm_h<1,__half>, cudaFuncAttributeMaxDynamicSharedMemorySize, SMEM);

    // fp16 conversions (rn), pack Wq|Wk and bq|bk
    {
        int n;
        n = ROWS * DIMS / 8;   conv_h_kernel<<<(n+255)/256, 256>>>(x,  pxh, n);
        n = DIMS * DIMS / 8;   conv_h_kernel<<<(n+255)/256, 256>>>(Wq, pwh + WQK_OFF, n);
        n = DIMS * DIMS / 8;   conv_h_kernel<<<(n+255)/256, 256>>>(Wk, pwh + WQK_OFF + DIMS*DIMS, n);
        n = FFD * DIMS / 8;    conv_h_kernel<<<(n+255)/256, 256>>>(W1, pwh + W1_OFF, n);
        n = DIMS * FFD / 8;    conv_h_kernel<<<(n+255)/256, 256>>>(W2, pwh + W2_OFF, n);
        pack_bias_kernel<<<(DIMS+255)/256, 256>>>(bq, bk);
    }

    // [q|k] = x @ [Wq|Wk]^T + [bq|bk]   (fused, N=2048, fp16 out)
    gemm_h<0,__half><<<dim3(2*DIMS/128, ROWS/256), 256, SMEM>>>(pxh, pwh + WQK_OFF, pbr, pqkh, 2*DIMS, DIMS);
    // LN(q), LN(k), forward FFTs (3 per 2 rows), Kx, Qf
    fft_fwd_kernel<<<ROWS/2, 256>>>(x, gq, betaq, gk, betak);
    // S = sum_s Kx (freq domain, coalesced)
    reduce_s_kernel<<<dim3(BATCH, 9), 256>>>();
    // mix = irfft x2 rows per FFT; x1 = LN(x + mix) (+fp16 copy)
    fft_inv_ln_kernel<<<ROWS/2, 256>>>(x, g0, beta0);
    // h = relu(x1 @ W1^T + b1) -> fp16
    gemm_h<1,__half><<<dim3(FFD/128, ROWS/256), 256, SMEM>>>(px1h, pwh + W1_OFF, b1, ph, FFD, DIMS);
    // ff = h @ W2^T + b2
    gemm_h<0,float><<<dim3(DIMS/128, ROWS/256), 256, SMEM>>>(ph, pwh + W2_OFF, b2, pff, DIMS, FFD);
    // out = LN(x1 + ff)
    resid_ln_kernel<<<ROWS, 512>>>(g1, beta1, out);
}

// round 11
// speedup vs baseline: 1.0798x; 1.0161x over previous
#include <cuda_runtime.h>
#include <cuda_fp16.h>
#include <math.h>
#include <stdint.h>

#define DIMS 1024
#define FFD  4096
#define BATCH 4
#define SEQ  4096
#define ROWS (BATCH*SEQ)   // 16384
#define NF   513           // rfft bins for N=1024

// ---------------- scratch (device globals; no allocation allowed) ----------------
__device__ __half g_qkh[(size_t)ROWS*2*DIMS];   // q | k packed, fp16 (G1 out)
__device__ __half g_x1h[(size_t)ROWS*DIMS];     // LN output, fp16 (GEMM2 input + residual)
__device__ __half g_ffh[(size_t)ROWS*DIMS];     // FFN out, fp16
__device__ __half g_h  [(size_t)ROWS*FFD];      // FFN hidden, fp16
__device__ __half g_xh [(size_t)ROWS*DIMS];     // x in fp16
__device__ __half g_wh [(size_t)(2*DIMS*DIMS + 2*DIMS*FFD)]; // Wqk | W1 | W2 fp16
__device__ float  g_br [2*DIMS];                // bq | bk packed
__device__ float2 g_kx[(size_t)ROWS*NF];
__device__ float2 g_qf[(size_t)ROWS*NF];
__device__ float2 g_sf[BATCH*NF];

#define WQK_OFF 0
#define W1_OFF  (2*DIMS*DIMS)
#define W2_OFF  (2*DIMS*DIMS + DIMS*FFD)

// ---------------- PTX helpers ----------------
__device__ __forceinline__ uint32_t smem_u32(const void* p) {
    uint32_t a;
    asm("{ .reg .u64 t; cvta.to.shared.u64 t, %1; cvt.u32.u64 %0, t; }" : "=r"(a) : "l"(p));
    return a;
}
__device__ __forceinline__ uint32_t h2_as_u32(__half2 h) {
    union { __half2 h; uint32_t u; } cvt;
    cvt.h = h;
    return cvt.u;
}
__device__ __forceinline__ void cp16(uint32_t dst, const void* src) {
    asm volatile("cp.async.cg.shared.global [%0], [%1], 16;" :: "r"(dst), "l"(src));
}
#define CP_COMMIT() asm volatile("cp.async.commit_group;" ::: "memory")
template<int N> __device__ __forceinline__ void cp_wait() {
    asm volatile("cp.async.wait_group %0;" :: "n"(N) : "memory");
}
__device__ __forceinline__ void mma_f16(float& c0, float& c1, float& c2, float& c3,
                                        uint32_t a0, uint32_t a1, uint32_t a2, uint32_t a3,
                                        uint32_t b0, uint32_t b1) {
    asm volatile(
        "mma.sync.aligned.m16n8k16.row.col.f32.f16.f16.f32 "
        "{%0,%1,%2,%3}, {%4,%5,%6,%7}, {%8,%9}, {%0,%1,%2,%3};"
        : "+f"(c0), "+f"(c1), "+f"(c2), "+f"(c3)
        : "r"(a0), "r"(a1), "r"(a2), "r"(a3), "r"(b0), "r"(b1));
}
__device__ __forceinline__ void ldsm_x4(uint32_t& r0, uint32_t& r1, uint32_t& r2, uint32_t& r3,
                                        uint32_t addr) {
    asm volatile("ldmatrix.sync.aligned.m8n8.x4.shared.b16 {%0,%1,%2,%3}, [%4];"
                 : "=r"(r0), "=r"(r1), "=r"(r2), "=r"(r3) : "r"(addr));
}

// ---------------- merged fp32->fp16 conversion + bias pack (one launch) ----------------
#define XB   8192   // x: 16M floats / (8*256)
#define WQB  512
#define WKB  512
#define W1B  2048
#define W2B  2048
#define BBLK 8      // bias: 2048 floats / 256
#define CONV_BLOCKS (XB + WQB + WKB + W1B + W2B + BBLK)

__global__ void __launch_bounds__(256) conv_all_kernel(
    const float* __restrict__ x,
    const float* __restrict__ Wq, const float* __restrict__ Wk,
    const float* __restrict__ W1, const float* __restrict__ W2,
    const float* __restrict__ bq, const float* __restrict__ bk,
    __half* __restrict__ xh, __half* __restrict__ wh)
{
    int bid = blockIdx.x;
    const float* src;
    __half* dst;
    int off;
    if (bid < XB)                        { src = x;  dst = xh;                              off = bid; }
    else if (bid < XB+WQB)               { src = Wq; dst = wh + WQK_OFF;                    off = bid - XB; }
    else if (bid < XB+WQB+WKB)           { src = Wk; dst = wh + WQK_OFF + DIMS*DIMS;        off = bid - (XB+WQB); }
    else if (bid < XB+WQB+WKB+W1B)       { src = W1; dst = wh + W1_OFF;                     off = bid - (XB+WQB+WKB); }
    else if (bid < XB+WQB+WKB+W1B+W2B)   { src = W2; dst = wh + W2_OFF;                     off = bid - (XB+WQB+WKB+W1B); }
    else {
        int i = (bid - (XB+WQB+WKB+W1B+W2B)) * 256 + threadIdx.x;
        if (i < DIMS) g_br[i] = bq[i];
        else          g_br[i] = bk[i - DIMS];
        return;
    }
    int i = off * 256 + threadIdx.x;
    float4 a = ((const float4*)src)[2*i];
    float4 b = ((const float4*)src)[2*i+1];
    uint4 o;
    o.x = h2_as_u32(__floats2half2_rn(a.x, a.y));
    o.y = h2_as_u32(__floats2half2_rn(a.z, a.w));
    o.z = h2_as_u32(__floats2half2_rn(b.x, b.y));
    o.w = h2_as_u32(__floats2half2_rn(b.z, b.w));
    ((uint4*)dst)[i] = o;
}

// ======================= mma.sync fp16 GEMM =======================
#define BK 64
#define ROWB 144
#define A_TILE_BYTES (256*ROWB)
#define B_TILE_BYTES (128*ROWB)
#define STAGE_BYTES (A_TILE_BYTES + B_TILE_BYTES)
#define NSTAGE 4

template<int RELU, typename CT>
__global__ void __launch_bounds__(256, 1)
gemm_h(const __half* __restrict__ A, const __half* __restrict__ B,
       const float* __restrict__ bias, CT* __restrict__ C,
       int N, int K)
{
    extern __shared__ char smem[];
    const int tid = threadIdx.x;
    const int warp = tid >> 5;
    const int lane = tid & 31;
    const int wm = warp >> 1;
    const int wn = warp & 1;
    const int lr = lane >> 2;
    const int lc = lane & 3;

    const __half* Ab = A + (size_t)blockIdx.y * 256 * K;
    const __half* Bb = B + (size_t)blockIdx.x * 128 * K;

    const uint32_t sbase = smem_u32(smem);
    const int ktiles = K / BK;

    uint32_t aoff[4];
    {
        const int l7 = lane & 7;
        const int rsel = (lane >> 3) & 1;
        const int csel = lane >> 4;
        #pragma unroll
        for (int mt = 0; mt < 4; mt++) {
            int r = wm * 64 + mt * 16 + l7 + rsel * 8;
            aoff[mt] = (uint32_t)(r * ROWB + csel * 16);
        }
    }
    uint32_t boff[4];
    {
        const int l7 = lane & 7;
        const int csel = (lane >> 3) & 1;
        const int rsel = lane >> 4;
        #pragma unroll
        for (int pr = 0; pr < 4; pr++) {
            int r = wn * 64 + pr * 16 + rsel * 8 + l7;
            boff[pr] = (uint32_t)(r * ROWB + csel * 16);
        }
    }

    auto load_stage = [&](int stage, int kt) {
        const int k0 = kt * BK;
        const uint32_t sA = sbase + stage * STAGE_BYTES;
        const uint32_t sB = sA + A_TILE_BYTES;
        #pragma unroll
        for (int i = 0; i < 8; i++) {
            int g = i * 256 + tid;
            int r = g >> 3, c = g & 7;
            cp16(sA + r * ROWB + c * 16, Ab + (size_t)r * K + k0 + c * 8);
        }
        #pragma unroll
        for (int i = 0; i < 4; i++) {
            int g = i * 256 + tid;
            int r = g >> 3, c = g & 7;
            cp16(sB + r * ROWB + c * 16, Bb + (size_t)r * K + k0 + c * 8);
        }
    };

    load_stage(0, 0); CP_COMMIT();
    load_stage(1, 1); CP_COMMIT();
    load_stage(2, 2); CP_COMMIT();

    float acc[4][8][4];
    #pragma unroll
    for (int i = 0; i < 4; i++)
        #pragma unroll
        for (int j = 0; j < 8; j++)
            #pragma unroll
            for (int r = 0; r < 4; r++) acc[i][j][r] = 0.f;

    for (int it = 0; it < ktiles; it++) {
        cp_wait<NSTAGE - 2>();
        __syncthreads();

        const uint32_t sA = sbase + (it % NSTAGE) * STAGE_BYTES;
        const uint32_t sB = sA + A_TILE_BYTES;

        const int nt3 = it + NSTAGE - 1;
        if (nt3 < ktiles) load_stage(nt3 % NSTAGE, nt3);
        CP_COMMIT();

        #pragma unroll
        for (int ks = 0; ks < 4; ks++) {
            const uint32_t kb = ks * 32;
            uint32_t a[4][4], b[8][2];
            #pragma unroll
            for (int mt = 0; mt < 4; mt++)
                ldsm_x4(a[mt][0], a[mt][1], a[mt][2], a[mt][3], sA + aoff[mt] + kb);
            #pragma unroll
            for (int pr = 0; pr < 4; pr++)
                ldsm_x4(b[2*pr][0], b[2*pr][1], b[2*pr+1][0], b[2*pr+1][1],
                        sB + boff[pr] + kb);
            #pragma unroll
            for (int mt = 0; mt < 4; mt++)
                #pragma unroll
                for (int nt = 0; nt < 8; nt++)
                    mma_f16(acc[mt][nt][0], acc[mt][nt][1],
                            acc[mt][nt][2], acc[mt][nt][3],
                            a[mt][0], a[mt][1], a[mt][2], a[mt][3],
                            b[nt][0], b[nt][1]);
        }
    }

    const int crow0 = blockIdx.y * 256 + wm * 64;
    const int ccol0 = blockIdx.x * 128 + wn * 64;
    float bb0[8], bb1[8];
    #pragma unroll
    for (int nt = 0; nt < 8; nt++) {
        bb0[nt] = __ldg(bias + ccol0 + nt * 8 + lc * 2);
        bb1[nt] = __ldg(bias + ccol0 + nt * 8 + lc * 2 + 1);
    }
    #pragma unroll
    for (int mt = 0; mt < 4; mt++) {
        #pragma unroll
        for (int nt = 0; nt < 8; nt++) {
            const int r0 = crow0 + mt * 16 + lr;
            const int c0 = ccol0 + nt * 8 + lc * 2;
            float v0 = acc[mt][nt][0] + bb0[nt];
            float v1 = acc[mt][nt][1] + bb1[nt];
            float v2 = acc[mt][nt][2] + bb0[nt];
            float v3 = acc[mt][nt][3] + bb1[nt];
            if (RELU) {
                v0 = fmaxf(v0, 0.f); v1 = fmaxf(v1, 0.f);
                v2 = fmaxf(v2, 0.f); v3 = fmaxf(v3, 0.f);
            }
            if (sizeof(CT) == 2) {
                *(__half2*)((__half*)C + (size_t)r0 * N + c0)       = __floats2half2_rn(v0, v1);
                *(__half2*)((__half*)C + (size_t)(r0 + 8) * N + c0) = __floats2half2_rn(v2, v3);
            } else {
                *(float2*)((float*)C + (size_t)r0 * N + c0)       = make_float2(v0, v1);
                *(float2*)((float*)C + (size_t)(r0 + 8) * N + c0) = make_float2(v2, v3);
            }
        }
    }
}

// ---------------- FFT path helpers ----------------
__device__ __forceinline__ float2 cmulf(float2 a, float2 b) {
    return make_float2(a.x*b.x - a.y*b.y, a.x*b.y + a.y*b.x);
}
#define F(i) ((i) ^ ((((i) >> 5) & 7) << 2))

__device__ __forceinline__ float2 block_sum2_256(float2 v, volatile float2* red) {
    int t = threadIdx.x;
    #pragma unroll
    for (int o = 16; o; o >>= 1) {
        v.x += __shfl_xor_sync(0xffffffffu, v.x, o);
        v.y += __shfl_xor_sync(0xffffffffu, v.y, o);
    }
    if ((t & 31) == 0) { red[t >> 5].x = v.x; red[t >> 5].y = v.y; }
    __syncthreads();
    if (t == 0) {
        float2 s = make_float2(0.f, 0.f);
        #pragma unroll
        for (int i = 0; i < 8; i++) { s.x += red[i].x; s.y += red[i].y; }
        red[0].x = s.x; red[0].y = s.y;
    }
    __syncthreads();
    float2 r = make_float2(red[0].x, red[0].y);
    __syncthreads();
    return r;
}

// 1024-pt radix-4 Stockham FFT (forward), 256 threads, 5 stages. Result in bufB.
__device__ __forceinline__ void fft1024_r4(float2* bufA, float2* bufB,
                                           const float2* tw, int v) {
    float2* src = bufA; float2* dst = bufB;
    #pragma unroll
    for (int st = 0; st < 5; st++) {
        const int ls = 2 * st;
        const int s = 1 << ls;
        const int idx = v & ~(s - 1);
        float2 w1 = tw[idx];
        float2 w2 = tw[2*idx];
        float2 w3 = tw[3*idx];
        float2 a = src[F(v)];
        float2 b = src[F(v + 256)];
        float2 c = src[F(v + 512)];
        float2 d = src[F(v + 768)];
        float2 apc = make_float2(a.x + c.x, a.y + c.y);
        float2 amc = make_float2(a.x - c.x, a.y - c.y);
        float2 bpd = make_float2(b.x + d.x, b.y + d.y);
        float2 jbmd = make_float2(-(b.y - d.y), b.x - d.x);
        const int bo = v + 3 * idx;
        dst[F(bo)]         = make_float2(apc.x + bpd.x, apc.y + bpd.y);
        dst[F(bo + s)]     = cmulf(w1, make_float2(amc.x - jbmd.x, amc.y - jbmd.y));
        dst[F(bo + 2*s)]   = cmulf(w2, make_float2(apc.x - bpd.x, apc.y - bpd.y));
        dst[F(bo + 3*s)]   = cmulf(w3, make_float2(amc.x + jbmd.x, amc.y + jbmd.y));
        __syncthreads();
        float2* tmp = src; src = dst; dst = tmp;
    }
}

// ---------------- forward: LN(q,k) x2 rows; 3 FFTs per 2 rows ----------------
__global__ void __launch_bounds__(256) fft_fwd_kernel(
    const float* __restrict__ x,
    const float* __restrict__ gq, const float* __restrict__ betaq,
    const float* __restrict__ gk, const float* __restrict__ betak)
{
    const int row0 = blockIdx.x * 2;
    const int row1 = row0 + 1;
    const int t = threadIdx.x;
    __shared__ float2 tw[768];
    __shared__ float2 bufA[1024];
    __shared__ float2 bufB[1024];
    __shared__ float2 red2[8];

    #pragma unroll
    for (int j = 0; j < 3; j++) {
        int i = t + 256 * j;
        float s_, c_;
        sincospif((float)i * (1.0f/512.0f), &s_, &c_);
        tw[i] = make_float2(c_, -s_);
    }

    const float invN = 1.0f / 1024.0f;
    float xv[2][4], qn[2][4], kn[2][4];
    #pragma unroll
    for (int r = 0; r < 2; r++) {
        const int row = row0 + r;
        const float*  xr = x     + (size_t)row * DIMS;
        const __half* qr = g_qkh + (size_t)row * 2 * DIMS;
        const __half* kr = qr + DIMS;
        float qv[4], kv[4];
        #pragma unroll
        for (int i = 0; i < 4; i++) {
            int e = t + 256 * i;
            xv[r][i] = xr[e];
            qv[i] = __half2float(qr[e]);
            kv[i] = __half2float(kr[e]);
        }
        float2 s1 = make_float2(0.f, 0.f), s2 = make_float2(0.f, 0.f);
        #pragma unroll
        for (int i = 0; i < 4; i++) {
            s1.x += qv[i]; s1.y += kv[i];
            s2.x += qv[i]*qv[i]; s2.y += kv[i]*kv[i];
        }
        s1 = block_sum2_256(s1, red2);
        s2 = block_sum2_256(s2, red2);
        float mq = s1.x * invN, vq = s2.x * invN - mq*mq;
        float rq = rsqrtf(vq + 1e-5f);
        float mk = s1.y * invN, vk = s2.y * invN - mk*mk;
        float rk = rsqrtf(vk + 1e-5f);
        #pragma unroll
        for (int i = 0; i < 4; i++) {
            int e = t + 256 * i;
            qn[r][i] = (qv[i] - mq) * rq * gq[e] + betaq[e];
            kn[r][i] = (kv[i] - mk) * rk * gk[e] + betak[e];
        }
    }

    // FFT of x_r + i*kn_r  ->  Kx row r   (two passes)
    #pragma unroll
    for (int r = 0; r < 2; r++) {
        const int row = row0 + r;
        #pragma unroll
        for (int i = 0; i < 4; i++) bufA[F(t + 256*i)] = make_float2(xv[r][i], kn[r][i]);
        __syncthreads();
        fft1024_r4(bufA, bufB, tw, t);
        #pragma unroll
        for (int jj = 0; jj < 2; jj++) {
            int j = t + 256 * jj;
            float2 z  = bufB[F(j)];
            float2 zn = bufB[F((1024 - j) & 1023)];
            float2 xf = make_float2(0.5f*(z.x + zn.x), 0.5f*(z.y - zn.y));
            float2 df = make_float2(z.x - zn.x, z.y + zn.y);
            float2 kf = make_float2(0.5f*df.y, -0.5f*df.x);
            g_kx[(size_t)row*NF + j] = cmulf(xf, kf);
        }
        if (t == 0) {
            float2 z5 = bufB[F(512)];
            g_kx[(size_t)row*NF + 512] = make_float2(z5.x * z5.y, 0.f);
        }
        __syncthreads();
    }

    // FFT of qn0 + i*qn1  ->  Qf rows row0, row1 (even/odd split)
    #pragma unroll
    for (int i = 0; i < 4; i++) bufA[F(t + 256*i)] = make_float2(qn[0][i], qn[1][i]);
    __syncthreads();
    fft1024_r4(bufA, bufB, tw, t);
    #pragma unroll
    for (int jj = 0; jj < 2; jj++) {
        int j = t + 256 * jj;
        float2 z  = bufB[F(j)];
        float2 zn = bufB[F((1024 - j) & 1023)];
        float2 q0 = make_float2(0.5f*(z.x + zn.x), 0.5f*(z.y - zn.y));
        float2 df = make_float2(z.x - zn.x, z.y + zn.y);
        float2 q1 = make_float2(0.5f*df.y, -0.5f*df.x);
        g_qf[(size_t)row0*NF + j] = q0;
        g_qf[(size_t)row1*NF + j] = q1;
    }
    if (t == 0) {
        float2 z5 = bufB[F(512)];
        g_qf[(size_t)row0*NF + 512] = make_float2(z5.x, 0.f);
        g_qf[(size_t)row1*NF + 512] = make_float2(z5.y, 0.f);
    }
}

// ---------------- reduce S_freq[b] = sum_s Kx[b,s]  (coalesced) ----------------
__global__ void __launch_bounds__(256) reduce_s_kernel() {
    const int b  = blockIdx.x;
    const int jc = blockIdx.y;
    const int t  = threadIdx.x;
    const int jl = t & 63;
    const int sl = t >> 6;
    const int j  = jc * 64 + jl;
    float2 acc = make_float2(0.f, 0.f);
    if (j < NF) {
        const float2* p = g_kx + (size_t)b * SEQ * NF + j;
        for (int s = sl; s < SEQ; s += 4) {
            float2 v = p[(size_t)s * NF];
            acc.x += v.x; acc.y += v.y;
        }
    }
    __shared__ float2 red[256];
    red[t] = acc;
    __syncthreads();
    if (t < 128) { red[t].x += red[t+128].x; red[t].y += red[t+128].y; }
    __syncthreads();
    if (t < 64) {
        red[t].x += red[t+64].x; red[t].y += red[t+64].y;
        if (j < NF) g_sf[b * NF + j] = red[t];
    }
}

// ---------------- inverse: 1 FFT per 2 rows; LN(x+mix) x2 -> fp16 x1 ----------------
__global__ void __launch_bounds__(256) fft_inv_ln_kernel(
    const float* __restrict__ x,
    const float* __restrict__ g0, const float* __restrict__ beta0)
{
    const int row0 = blockIdx.x * 2;
    const int row1 = row0 + 1;
    const int b = row0 >> 12;
    const int t = threadIdx.x;
    __shared__ float2 tw[768];
    __shared__ float2 bufA[1024];
    __shared__ float2 bufB[1024];
    __shared__ float2 red2[8];

    #pragma unroll
    for (int j = 0; j < 3; j++) {
        int i = t + 256 * j;
        float s_, c_;
        sincospif((float)i * (1.0f/512.0f), &s_, &c_);
        tw[i] = make_float2(c_, -s_);
    }

    #pragma unroll
    for (int jj = 0; jj < 2; jj++) {
        int j = t + 256 * jj;
        float2 sf = g_sf[b*NF + j];
        float2 kx0 = g_kx[(size_t)row0*NF + j];
        float2 qf0 = g_qf[(size_t)row0*NF + j];
        float2 m0 = make_float2(kx0.x + sf.x*qf0.x + sf.y*qf0.y,
                                kx0.y - sf.x*qf0.y + sf.y*qf0.x);
        float2 kx1 = g_kx[(size_t)row1*NF + j];
        float2 qf1 = g_qf[(size_t)row1*NF + j];
        float2 m1 = make_float2(kx1.x + sf.x*qf1.x + sf.y*qf1.y,
                                kx1.y - sf.x*qf1.y + sf.y*qf1.x);
        bufA[F(j)] = make_float2(m0.x - m1.y, -m0.y - m1.x);
        if (j > 0) bufA[F(1024 - j)] = make_float2(m0.x + m1.y, m0.y - m1.x);
    }
    if (t == 0) {
        float2 sf = g_sf[b*NF + 512];
        float2 kx0 = g_kx[(size_t)row0*NF + 512];
        float2 qf0 = g_qf[(size_t)row0*NF + 512];
        float m0 = kx0.x + sf.x*qf0.x;
        float2 kx1 = g_kx[(size_t)row1*NF + 512];
        float2 qf1 = g_qf[(size_t)row1*NF + 512];
        float m1 = kx1.x + sf.x*qf1.x;
        bufA[F(512)] = make_float2(m0, -m1);
    }
    __syncthreads();
    fft1024_r4(bufA, bufB, tw, t);

    const float invN = 1.0f / 1024.0f;
    #pragma unroll
    for (int r = 0; r < 2; r++) {
        const int row = row0 + r;
        const float* xr = x + (size_t)row * DIMS;
        float y[4];
        float2 s12 = make_float2(0.f, 0.f);
        #pragma unroll
        for (int i = 0; i < 4; i++) {
            int e = t + 256 * i;
            float2 w = bufB[F(e)];
            float mixv = (r == 0 ? w.x : -w.y) * invN;
            y[i] = xr[e] + mixv;
            s12.x += y[i];
            s12.y += y[i] * y[i];
        }
        s12 = block_sum2_256(s12, red2);
        float m = s12.x * invN, v = s12.y * invN - m*m;
        float rr = rsqrtf(v + 1e-5f);
        __half* oh = g_x1h + (size_t)row * DIMS;
        #pragma unroll
        for (int i = 0; i < 4; i++) {
            int e = t + 256 * i;
            float ov = (y[i] - m) * rr * g0[e] + beta0[e];
            oh[e] = __float2half_rn(ov);
        }
    }
}

// ---------------- out = LN(x1 + ff)  (fp16 inputs) ----------------
__device__ __forceinline__ float block_sum512(float v, volatile float* red) {
    int t = threadIdx.x;
    #pragma unroll
    for (int o = 16; o; o >>= 1) v += __shfl_xor_sync(0xffffffffu, v, o);
    if ((t & 31) == 0) red[t >> 5] = v;
    __syncthreads();
    if (t == 0) {
        float s = 0.f;
        #pragma unroll
        for (int i = 0; i < 16; i++) s += red[i];
        red[0] = s;
    }
    __syncthreads();
    float r = red[0];
    __syncthreads();
    return r;
}

__global__ void __launch_bounds__(512) resid_ln_kernel(
    const float* __restrict__ g1v, const float* __restrict__ beta1,
    float* __restrict__ out)
{
    const int row = blockIdx.x;
    const int t = threadIdx.x;
    __shared__ float red[16];
    const __half* a = g_x1h + (size_t)row * DIMS;
    const __half* f = g_ffh + (size_t)row * DIMS;
    float y0 = __half2float(a[t])     + __half2float(f[t]);
    float y1 = __half2float(a[t+512]) + __half2float(f[t+512]);
    const float invN = 1.0f / 1024.0f;
    float s  = block_sum512(y0 + y1, red);
    float ss = block_sum512(y0*y0 + y1*y1, red);
    float m = s * invN, v = ss * invN - m*m;
    float r = rsqrtf(v + 1e-5f);
    float* o = out + (size_t)row * DIMS;
    o[t]     = (y0 - m) * r * g1v[t]     + beta1[t];
    o[t+512] = (y1 - m) * r * g1v[t+512] + beta1[t+512];
}

// ---------------- launch ----------------
extern "C" void kernel_launch(void* const* d_in, const int* in_sizes, int n_in,
                              void* d_out, int out_size)
{
    const float* x     = (const float*)d_in[0];
    const float* Wq    = (const float*)d_in[1];
    const float* bq    = (const float*)d_in[2];
    const float* gq    = (const float*)d_in[3];
    const float* betaq = (const float*)d_in[4];
    const float* Wk    = (const float*)d_in[5];
    const float* bk    = (const float*)d_in[6];
    const float* gk    = (const float*)d_in[7];
    const float* betak = (const float*)d_in[8];
    const float* g0    = (const float*)d_in[9];
    const float* beta0 = (const float*)d_in[10];
    const float* W1    = (const float*)d_in[11];
    const float* b1    = (const float*)d_in[12];
    const float* W2    = (const float*)d_in[13];
    const float* b2    = (const float*)d_in[14];
    const float* g1    = (const float*)d_in[15];
    const float* beta1 = (const float*)d_in[16];
    float* out = (float*)d_out;

    float *pbr;
    __half *pqkh, *px1h, *ph, *pxh, *pwh, *pffh;
    cudaGetSymbolAddress((void**)&pqkh, g_qkh);
    cudaGetSymbolAddress((void**)&px1h, g_x1h);
    cudaGetSymbolAddress((void**)&ph,   g_h);
    cudaGetSymbolAddress((void**)&pffh, g_ffh);
    cudaGetSymbolAddress((void**)&pxh,  g_xh);
    cudaGetSymbolAddress((void**)&pwh,  g_wh);
    cudaGetSymbolAddress((void**)&pbr,  g_br);

    const int SMEM = NSTAGE * STAGE_BYTES;  // 221184 B
    cudaFuncSetAttribute(gemm_h<0,__half>, cudaFuncAttributeMaxDynamicSharedMemorySize, SMEM);
    cudaFuncSetAttribute(gemm_h<1,__half>, cudaFuncAttributeMaxDynamicSharedMemorySize, SMEM);

    // all fp32->fp16 conversions + bias pack in one launch
    conv_all_kernel<<<CONV_BLOCKS, 256>>>(x, Wq, Wk, W1, W2, bq, bk, pxh, pwh);

    // [q|k] = x @ [Wq|Wk]^T + [bq|bk]   (fused, N=2048, fp16 out)
    gemm_h<0,__half><<<dim3(2*DIMS/128, ROWS/256), 256, SMEM>>>(pxh, pwh + WQK_OFF, pbr, pqkh, 2*DIMS, DIMS);
    // LN(q), LN(k), forward FFTs (3 per 2 rows), Kx, Qf
    fft_fwd_kernel<<<ROWS/2, 256>>>(x, gq, betaq, gk, betak);
    // S = sum_s Kx (freq domain, coalesced)
    reduce_s_kernel<<<dim3(BATCH, 9), 256>>>();
    // mix = irfft x2 rows per FFT; x1 = LN(x + mix) -> fp16
    fft_inv_ln_kernel<<<ROWS/2, 256>>>(x, g0, beta0);
    // h = relu(x1 @ W1^T + b1) -> fp16
    gemm_h<1,__half><<<dim3(FFD/128, ROWS/256), 256, SMEM>>>(px1h, pwh + W1_OFF, b1, ph, FFD, DIMS);
    // ff = h @ W2^T + b2 -> fp16
    gemm_h<0,__half><<<dim3(DIMS/128, ROWS/256), 256, SMEM>>>(ph, pwh + W2_OFF, b2, pffh, DIMS, FFD);
    // out = LN(x1 + ff)
    resid_ln_kernel<<<ROWS, 512>>>(g1, beta1, out);
}

// round 12
// speedup vs baseline: 1.1334x; 1.0497x over previous
#include <cuda_runtime.h>
#include <cuda_fp16.h>
#include <math.h>
#include <stdint.h>

#define DIMS 1024
#define FFD  4096
#define BATCH 4
#define SEQ  4096
#define ROWS (BATCH*SEQ)   // 16384
#define NF   513           // rfft bins for N=1024
#define SCHUNK 32          // seq chunks for reduce stage 1

// ---------------- scratch (device globals; no allocation allowed) ----------------
__device__ __half g_qkh[(size_t)ROWS*2*DIMS];   // q | k packed, fp16 (G1 out)
__device__ __half g_x1h[(size_t)ROWS*DIMS];     // LN output, fp16
__device__ __half g_ffh[(size_t)ROWS*DIMS];     // FFN out, fp16
__device__ __half g_h  [(size_t)ROWS*FFD];      // FFN hidden, fp16
__device__ __half g_xh [(size_t)ROWS*DIMS];     // x in fp16
__device__ __half g_wh [(size_t)(2*DIMS*DIMS + 2*DIMS*FFD)]; // Wqk | W1 | W2 fp16
__device__ float  g_br [2*DIMS];                // bq | bk packed
__device__ float2 g_kx[(size_t)ROWS*NF];
__device__ float2 g_qf[(size_t)ROWS*NF];
__device__ float2 g_sf[BATCH*NF];
__device__ float2 g_sp[SCHUNK*BATCH*NF];        // stage-1 partials

#define WQK_OFF 0
#define W1_OFF  (2*DIMS*DIMS)
#define W2_OFF  (2*DIMS*DIMS + DIMS*FFD)

// ---------------- PTX helpers ----------------
__device__ __forceinline__ uint32_t smem_u32(const void* p) {
    uint32_t a;
    asm("{ .reg .u64 t; cvta.to.shared.u64 t, %1; cvt.u32.u64 %0, t; }" : "=r"(a) : "l"(p));
    return a;
}
__device__ __forceinline__ uint32_t h2_as_u32(__half2 h) {
    union { __half2 h; uint32_t u; } cvt;
    cvt.h = h;
    return cvt.u;
}
__device__ __forceinline__ void cp16(uint32_t dst, const void* src) {
    asm volatile("cp.async.cg.shared.global [%0], [%1], 16;" :: "r"(dst), "l"(src));
}
#define CP_COMMIT() asm volatile("cp.async.commit_group;" ::: "memory")
template<int N> __device__ __forceinline__ void cp_wait() {
    asm volatile("cp.async.wait_group %0;" :: "n"(N) : "memory");
}
__device__ __forceinline__ void mma_f16(float& c0, float& c1, float& c2, float& c3,
                                        uint32_t a0, uint32_t a1, uint32_t a2, uint32_t a3,
                                        uint32_t b0, uint32_t b1) {
    asm volatile(
        "mma.sync.aligned.m16n8k16.row.col.f32.f16.f16.f32 "
        "{%0,%1,%2,%3}, {%4,%5,%6,%7}, {%8,%9}, {%0,%1,%2,%3};"
        : "+f"(c0), "+f"(c1), "+f"(c2), "+f"(c3)
        : "r"(a0), "r"(a1), "r"(a2), "r"(a3), "r"(b0), "r"(b1));
}
__device__ __forceinline__ void ldsm_x4(uint32_t& r0, uint32_t& r1, uint32_t& r2, uint32_t& r3,
                                        uint32_t addr) {
    asm volatile("ldmatrix.sync.aligned.m8n8.x4.shared.b16 {%0,%1,%2,%3}, [%4];"
                 : "=r"(r0), "=r"(r1), "=r"(r2), "=r"(r3) : "r"(addr));
}

// ---------------- merged fp32->fp16 conversion + bias pack (one launch) ----------------
#define XB   8192
#define WQB  512
#define WKB  512
#define W1B  2048
#define W2B  2048
#define BBLK 8
#define CONV_BLOCKS (XB + WQB + WKB + W1B + W2B + BBLK)

__global__ void __launch_bounds__(256) conv_all_kernel(
    const float* __restrict__ x,
    const float* __restrict__ Wq, const float* __restrict__ Wk,
    const float* __restrict__ W1, const float* __restrict__ W2,
    const float* __restrict__ bq, const float* __restrict__ bk,
    __half* __restrict__ xh, __half* __restrict__ wh)
{
    int bid = blockIdx.x;
    const float* src;
    __half* dst;
    int off;
    if (bid < XB)                        { src = x;  dst = xh;                       off = bid; }
    else if (bid < XB+WQB)               { src = Wq; dst = wh + WQK_OFF;             off = bid - XB; }
    else if (bid < XB+WQB+WKB)           { src = Wk; dst = wh + WQK_OFF + DIMS*DIMS; off = bid - (XB+WQB); }
    else if (bid < XB+WQB+WKB+W1B)       { src = W1; dst = wh + W1_OFF;              off = bid - (XB+WQB+WKB); }
    else if (bid < XB+WQB+WKB+W1B+W2B)   { src = W2; dst = wh + W2_OFF;              off = bid - (XB+WQB+WKB+W1B); }
    else {
        int i = (bid - (XB+WQB+WKB+W1B+W2B)) * 256 + threadIdx.x;
        if (i < DIMS) g_br[i] = bq[i];
        else          g_br[i] = bk[i - DIMS];
        return;
    }
    int i = off * 256 + threadIdx.x;
    float4 a = ((const float4*)src)[2*i];
    float4 b = ((const float4*)src)[2*i+1];
    uint4 o;
    o.x = h2_as_u32(__floats2half2_rn(a.x, a.y));
    o.y = h2_as_u32(__floats2half2_rn(a.z, a.w));
    o.z = h2_as_u32(__floats2half2_rn(b.x, b.y));
    o.w = h2_as_u32(__floats2half2_rn(b.z, b.w));
    ((uint4*)dst)[i] = o;
}

// ======================= mma.sync fp16 GEMM =======================
#define BK 64
#define ROWB 144
#define A_TILE_BYTES (256*ROWB)
#define B_TILE_BYTES (128*ROWB)
#define STAGE_BYTES (A_TILE_BYTES + B_TILE_BYTES)
#define NSTAGE 4

template<int RELU, typename CT>
__global__ void __launch_bounds__(256, 1)
gemm_h(const __half* __restrict__ A, const __half* __restrict__ B,
       const float* __restrict__ bias, CT* __restrict__ C,
       int N, int K)
{
    extern __shared__ char smem[];
    const int tid = threadIdx.x;
    const int warp = tid >> 5;
    const int lane = tid & 31;
    const int wm = warp >> 1;
    const int wn = warp & 1;
    const int lr = lane >> 2;
    const int lc = lane & 3;

    const __half* Ab = A + (size_t)blockIdx.y * 256 * K;
    const __half* Bb = B + (size_t)blockIdx.x * 128 * K;

    const uint32_t sbase = smem_u32(smem);
    const int ktiles = K / BK;

    uint32_t aoff[4];
    {
        const int l7 = lane & 7;
        const int rsel = (lane >> 3) & 1;
        const int csel = lane >> 4;
        #pragma unroll
        for (int mt = 0; mt < 4; mt++) {
            int r = wm * 64 + mt * 16 + l7 + rsel * 8;
            aoff[mt] = (uint32_t)(r * ROWB + csel * 16);
        }
    }
    uint32_t boff[4];
    {
        const int l7 = lane & 7;
        const int csel = (lane >> 3) & 1;
        const int rsel = lane >> 4;
        #pragma unroll
        for (int pr = 0; pr < 4; pr++) {
            int r = wn * 64 + pr * 16 + rsel * 8 + l7;
            boff[pr] = (uint32_t)(r * ROWB + csel * 16);
        }
    }

    auto load_stage = [&](int stage, int kt) {
        const int k0 = kt * BK;
        const uint32_t sA = sbase + stage * STAGE_BYTES;
        const uint32_t sB = sA + A_TILE_BYTES;
        #pragma unroll
        for (int i = 0; i < 8; i++) {
            int g = i * 256 + tid;
            int r = g >> 3, c = g & 7;
            cp16(sA + r * ROWB + c * 16, Ab + (size_t)r * K + k0 + c * 8);
        }
        #pragma unroll
        for (int i = 0; i < 4; i++) {
            int g = i * 256 + tid;
            int r = g >> 3, c = g & 7;
            cp16(sB + r * ROWB + c * 16, Bb + (size_t)r * K + k0 + c * 8);
        }
    };

    load_stage(0, 0); CP_COMMIT();
    load_stage(1, 1); CP_COMMIT();
    load_stage(2, 2); CP_COMMIT();

    float acc[4][8][4];
    #pragma unroll
    for (int i = 0; i < 4; i++)
        #pragma unroll
        for (int j = 0; j < 8; j++)
            #pragma unroll
            for (int r = 0; r < 4; r++) acc[i][j][r] = 0.f;

    for (int it = 0; it < ktiles; it++) {
        cp_wait<NSTAGE - 2>();
        __syncthreads();

        const uint32_t sA = sbase + (it % NSTAGE) * STAGE_BYTES;
        const uint32_t sB = sA + A_TILE_BYTES;

        const int nt3 = it + NSTAGE - 1;
        if (nt3 < ktiles) load_stage(nt3 % NSTAGE, nt3);
        CP_COMMIT();

        #pragma unroll
        for (int ks = 0; ks < 4; ks++) {
            const uint32_t kb = ks * 32;
            uint32_t a[4][4], b[8][2];
            #pragma unroll
            for (int mt = 0; mt < 4; mt++)
                ldsm_x4(a[mt][0], a[mt][1], a[mt][2], a[mt][3], sA + aoff[mt] + kb);
            #pragma unroll
            for (int pr = 0; pr < 4; pr++)
                ldsm_x4(b[2*pr][0], b[2*pr][1], b[2*pr+1][0], b[2*pr+1][1],
                        sB + boff[pr] + kb);
            #pragma unroll
            for (int mt = 0; mt < 4; mt++)
                #pragma unroll
                for (int nt = 0; nt < 8; nt++)
                    mma_f16(acc[mt][nt][0], acc[mt][nt][1],
                            acc[mt][nt][2], acc[mt][nt][3],
                            a[mt][0], a[mt][1], a[mt][2], a[mt][3],
                            b[nt][0], b[nt][1]);
        }
    }

    const int crow0 = blockIdx.y * 256 + wm * 64;
    const int ccol0 = blockIdx.x * 128 + wn * 64;
    float bb0[8], bb1[8];
    #pragma unroll
    for (int nt = 0; nt < 8; nt++) {
        bb0[nt] = __ldg(bias + ccol0 + nt * 8 + lc * 2);
        bb1[nt] = __ldg(bias + ccol0 + nt * 8 + lc * 2 + 1);
    }
    #pragma unroll
    for (int mt = 0; mt < 4; mt++) {
        #pragma unroll
        for (int nt = 0; nt < 8; nt++) {
            const int r0 = crow0 + mt * 16 + lr;
            const int c0 = ccol0 + nt * 8 + lc * 2;
            float v0 = acc[mt][nt][0] + bb0[nt];
            float v1 = acc[mt][nt][1] + bb1[nt];
            float v2 = acc[mt][nt][2] + bb0[nt];
            float v3 = acc[mt][nt][3] + bb1[nt];
            if (RELU) {
                v0 = fmaxf(v0, 0.f); v1 = fmaxf(v1, 0.f);
                v2 = fmaxf(v2, 0.f); v3 = fmaxf(v3, 0.f);
            }
            if (sizeof(CT) == 2) {
                *(__half2*)((__half*)C + (size_t)r0 * N + c0)       = __floats2half2_rn(v0, v1);
                *(__half2*)((__half*)C + (size_t)(r0 + 8) * N + c0) = __floats2half2_rn(v2, v3);
            } else {
                *(float2*)((float*)C + (size_t)r0 * N + c0)       = make_float2(v0, v1);
                *(float2*)((float*)C + (size_t)(r0 + 8) * N + c0) = make_float2(v2, v3);
            }
        }
    }
}

// ---------------- FFT path helpers ----------------
__device__ __forceinline__ float2 cmulf(float2 a, float2 b) {
    return make_float2(a.x*b.x - a.y*b.y, a.x*b.y + a.y*b.x);
}
#define F(i) ((i) ^ ((((i) >> 5) & 7) << 2))

__device__ __forceinline__ float2 block_sum2_256(float2 v, volatile float2* red) {
    int t = threadIdx.x;
    #pragma unroll
    for (int o = 16; o; o >>= 1) {
        v.x += __shfl_xor_sync(0xffffffffu, v.x, o);
        v.y += __shfl_xor_sync(0xffffffffu, v.y, o);
    }
    if ((t & 31) == 0) { red[t >> 5].x = v.x; red[t >> 5].y = v.y; }
    __syncthreads();
    if (t == 0) {
        float2 s = make_float2(0.f, 0.f);
        #pragma unroll
        for (int i = 0; i < 8; i++) { s.x += red[i].x; s.y += red[i].y; }
        red[0].x = s.x; red[0].y = s.y;
    }
    __syncthreads();
    float2 r = make_float2(red[0].x, red[0].y);
    __syncthreads();
    return r;
}

// 1024-pt radix-4 Stockham FFT (forward), 256 threads, 5 stages. Result in bufB.
__device__ __forceinline__ void fft1024_r4(float2* bufA, float2* bufB,
                                           const float2* tw, int v) {
    float2* src = bufA; float2* dst = bufB;
    #pragma unroll
    for (int st = 0; st < 5; st++) {
        const int ls = 2 * st;
        const int s = 1 << ls;
        const int idx = v & ~(s - 1);
        float2 w1 = tw[idx];
        float2 w2 = tw[2*idx];
        float2 w3 = tw[3*idx];
        float2 a = src[F(v)];
        float2 b = src[F(v + 256)];
        float2 c = src[F(v + 512)];
        float2 d = src[F(v + 768)];
        float2 apc = make_float2(a.x + c.x, a.y + c.y);
        float2 amc = make_float2(a.x - c.x, a.y - c.y);
        float2 bpd = make_float2(b.x + d.x, b.y + d.y);
        float2 jbmd = make_float2(-(b.y - d.y), b.x - d.x);
        const int bo = v + 3 * idx;
        dst[F(bo)]         = make_float2(apc.x + bpd.x, apc.y + bpd.y);
        dst[F(bo + s)]     = cmulf(w1, make_float2(amc.x - jbmd.x, amc.y - jbmd.y));
        dst[F(bo + 2*s)]   = cmulf(w2, make_float2(apc.x - bpd.x, apc.y - bpd.y));
        dst[F(bo + 3*s)]   = cmulf(w3, make_float2(amc.x + jbmd.x, amc.y + jbmd.y));
        __syncthreads();
        float2* tmp = src; src = dst; dst = tmp;
    }
}

// ---------------- forward: LN(q,k) x2 rows; 3 FFTs per 2 rows ----------------
__global__ void __launch_bounds__(256) fft_fwd_kernel(
    const float* __restrict__ x,
    const float* __restrict__ gq, const float* __restrict__ betaq,
    const float* __restrict__ gk, const float* __restrict__ betak)
{
    const int row0 = blockIdx.x * 2;
    const int row1 = row0 + 1;
    const int t = threadIdx.x;
    __shared__ float2 tw[768];
    __shared__ float2 bufA[1024];
    __shared__ float2 bufB[1024];
    __shared__ float2 red2[8];

    #pragma unroll
    for (int j = 0; j < 3; j++) {
        int i = t + 256 * j;
        float s_, c_;
        sincospif((float)i * (1.0f/512.0f), &s_, &c_);
        tw[i] = make_float2(c_, -s_);
    }

    const float invN = 1.0f / 1024.0f;
    float xv[2][4], qn[2][4], kn[2][4];
    #pragma unroll
    for (int r = 0; r < 2; r++) {
        const int row = row0 + r;
        const float*  xr = x     + (size_t)row * DIMS;
        const __half* qr = g_qkh + (size_t)row * 2 * DIMS;
        const __half* kr = qr + DIMS;
        float qv[4], kv[4];
        #pragma unroll
        for (int i = 0; i < 4; i++) {
            int e = t + 256 * i;
            xv[r][i] = xr[e];
            qv[i] = __half2float(qr[e]);
            kv[i] = __half2float(kr[e]);
        }
        float2 s1 = make_float2(0.f, 0.f), s2 = make_float2(0.f, 0.f);
        #pragma unroll
        for (int i = 0; i < 4; i++) {
            s1.x += qv[i]; s1.y += kv[i];
            s2.x += qv[i]*qv[i]; s2.y += kv[i]*kv[i];
        }
        s1 = block_sum2_256(s1, red2);
        s2 = block_sum2_256(s2, red2);
        float mq = s1.x * invN, vq = s2.x * invN - mq*mq;
        float rq = rsqrtf(vq + 1e-5f);
        float mk = s1.y * invN, vk = s2.y * invN - mk*mk;
        float rk = rsqrtf(vk + 1e-5f);
        #pragma unroll
        for (int i = 0; i < 4; i++) {
            int e = t + 256 * i;
            qn[r][i] = (qv[i] - mq) * rq * gq[e] + betaq[e];
            kn[r][i] = (kv[i] - mk) * rk * gk[e] + betak[e];
        }
    }

    #pragma unroll
    for (int r = 0; r < 2; r++) {
        const int row = row0 + r;
        #pragma unroll
        for (int i = 0; i < 4; i++) bufA[F(t + 256*i)] = make_float2(xv[r][i], kn[r][i]);
        __syncthreads();
        fft1024_r4(bufA, bufB, tw, t);
        #pragma unroll
        for (int jj = 0; jj < 2; jj++) {
            int j = t + 256 * jj;
            float2 z  = bufB[F(j)];
            float2 zn = bufB[F((1024 - j) & 1023)];
            float2 xf = make_float2(0.5f*(z.x + zn.x), 0.5f*(z.y - zn.y));
            float2 df = make_float2(z.x - zn.x, z.y + zn.y);
            float2 kf = make_float2(0.5f*df.y, -0.5f*df.x);
            g_kx[(size_t)row*NF + j] = cmulf(xf, kf);
        }
        if (t == 0) {
            float2 z5 = bufB[F(512)];
            g_kx[(size_t)row*NF + 512] = make_float2(z5.x * z5.y, 0.f);
        }
        __syncthreads();
    }

    #pragma unroll
    for (int i = 0; i < 4; i++) bufA[F(t + 256*i)] = make_float2(qn[0][i], qn[1][i]);
    __syncthreads();
    fft1024_r4(bufA, bufB, tw, t);
    #pragma unroll
    for (int jj = 0; jj < 2; jj++) {
        int j = t + 256 * jj;
        float2 z  = bufB[F(j)];
        float2 zn = bufB[F((1024 - j) & 1023)];
        float2 q0 = make_float2(0.5f*(z.x + zn.x), 0.5f*(z.y - zn.y));
        float2 df = make_float2(z.x - zn.x, z.y + zn.y);
        float2 q1 = make_float2(0.5f*df.y, -0.5f*df.x);
        g_qf[(size_t)row0*NF + j] = q0;
        g_qf[(size_t)row1*NF + j] = q1;
    }
    if (t == 0) {
        float2 z5 = bufB[F(512)];
        g_qf[(size_t)row0*NF + 512] = make_float2(z5.x, 0.f);
        g_qf[(size_t)row1*NF + 512] = make_float2(z5.y, 0.f);
    }
}

// ---------------- reduce S stage 1: partials over 128-seq chunks ----------------
__global__ void __launch_bounds__(256) reduce_s1_kernel() {
    const int b  = blockIdx.x;          // batch
    const int jc = blockIdx.y;          // 0..8  (64 bins each)
    const int sc = blockIdx.z;          // 0..31 (seq chunk of 128)
    const int t  = threadIdx.x;
    const int jl = t & 63;
    const int sl = t >> 6;              // 0..3
    const int j  = jc * 64 + jl;
    float2 acc = make_float2(0.f, 0.f);
    if (j < NF) {
        const int s0 = sc * 128;
        const float2* p = g_kx + (size_t)b * SEQ * NF + (size_t)s0 * NF + j;
        for (int s = sl; s < 128; s += 4) {
            float2 v = p[(size_t)s * NF];
            acc.x += v.x; acc.y += v.y;
        }
    }
    __shared__ float2 red[256];
    red[t] = acc;
    __syncthreads();
    if (t < 128) { red[t].x += red[t+128].x; red[t].y += red[t+128].y; }
    __syncthreads();
    if (t < 64) {
        red[t].x += red[t+64].x; red[t].y += red[t+64].y;
        if (j < NF) g_sp[((size_t)sc * BATCH + b) * NF + j] = red[t];
    }
}
// ---------------- reduce S stage 2: fold 32 partials ----------------
__global__ void __launch_bounds__(64) reduce_s2_kernel() {
    const int b  = blockIdx.x;
    const int jc = blockIdx.y;
    const int j  = jc * 64 + threadIdx.x;
    if (j >= NF) return;
    float2 acc = make_float2(0.f, 0.f);
    #pragma unroll
    for (int sc = 0; sc < SCHUNK; sc++) {
        float2 v = g_sp[((size_t)sc * BATCH + b) * NF + j];
        acc.x += v.x; acc.y += v.y;
    }
    g_sf[b * NF + j] = acc;
}

// ---------------- inverse: 1 FFT per 2 rows; LN(x+mix) x2 -> fp16 x1 ----------------
__global__ void __launch_bounds__(256) fft_inv_ln_kernel(
    const float* __restrict__ x,
    const float* __restrict__ g0, const float* __restrict__ beta0)
{
    const int row0 = blockIdx.x * 2;
    const int row1 = row0 + 1;
    const int b = row0 >> 12;
    const int t = threadIdx.x;
    __shared__ float2 tw[768];
    __shared__ float2 bufA[1024];
    __shared__ float2 bufB[1024];
    __shared__ float2 red2[8];

    #pragma unroll
    for (int j = 0; j < 3; j++) {
        int i = t + 256 * j;
        float s_, c_;
        sincospif((float)i * (1.0f/512.0f), &s_, &c_);
        tw[i] = make_float2(c_, -s_);
    }

    #pragma unroll
    for (int jj = 0; jj < 2; jj++) {
        int j = t + 256 * jj;
        float2 sf = g_sf[b*NF + j];
        float2 kx0 = g_kx[(size_t)row0*NF + j];
        float2 qf0 = g_qf[(size_t)row0*NF + j];
        float2 m0 = make_float2(kx0.x + sf.x*qf0.x + sf.y*qf0.y,
                                kx0.y - sf.x*qf0.y + sf.y*qf0.x);
        float2 kx1 = g_kx[(size_t)row1*NF + j];
        float2 qf1 = g_qf[(size_t)row1*NF + j];
        float2 m1 = make_float2(kx1.x + sf.x*qf1.x + sf.y*qf1.y,
                                kx1.y - sf.x*qf1.y + sf.y*qf1.x);
        bufA[F(j)] = make_float2(m0.x - m1.y, -m0.y - m1.x);
        if (j > 0) bufA[F(1024 - j)] = make_float2(m0.x + m1.y, m0.y - m1.x);
    }
    if (t == 0) {
        float2 sf = g_sf[b*NF + 512];
        float2 kx0 = g_kx[(size_t)row0*NF + 512];
        float2 qf0 = g_qf[(size_t)row0*NF + 512];
        float m0 = kx0.x + sf.x*qf0.x;
        float2 kx1 = g_kx[(size_t)row1*NF + 512];
        float2 qf1 = g_qf[(size_t)row1*NF + 512];
        float m1 = kx1.x + sf.x*qf1.x;
        bufA[F(512)] = make_float2(m0, -m1);
    }
    __syncthreads();
    fft1024_r4(bufA, bufB, tw, t);

    const float invN = 1.0f / 1024.0f;
    #pragma unroll
    for (int r = 0; r < 2; r++) {
        const int row = row0 + r;
        const float* xr = x + (size_t)row * DIMS;
        float y[4];
        float2 s12 = make_float2(0.f, 0.f);
        #pragma unroll
        for (int i = 0; i < 4; i++) {
            int e = t + 256 * i;
            float2 w = bufB[F(e)];
            float mixv = (r == 0 ? w.x : -w.y) * invN;
            y[i] = xr[e] + mixv;
            s12.x += y[i];
            s12.y += y[i] * y[i];
        }
        s12 = block_sum2_256(s12, red2);
        float m = s12.x * invN, v = s12.y * invN - m*m;
        float rr = rsqrtf(v + 1e-5f);
        __half* oh = g_x1h + (size_t)row * DIMS;
        #pragma unroll
        for (int i = 0; i < 4; i++) {
            int e = t + 256 * i;
            float ov = (y[i] - m) * rr * g0[e] + beta0[e];
            oh[e] = __float2half_rn(ov);
        }
    }
}

// ---------------- out = LN(x1 + ff)  (fp16 inputs, half2 vectorized) ----------------
__device__ __forceinline__ float block_sum512(float v, volatile float* red) {
    int t = threadIdx.x;
    #pragma unroll
    for (int o = 16; o; o >>= 1) v += __shfl_xor_sync(0xffffffffu, v, o);
    if ((t & 31) == 0) red[t >> 5] = v;
    __syncthreads();
    if (t == 0) {
        float s = 0.f;
        #pragma unroll
        for (int i = 0; i < 16; i++) s += red[i];
        red[0] = s;
    }
    __syncthreads();
    float r = red[0];
    __syncthreads();
    return r;
}

__global__ void __launch_bounds__(512) resid_ln_kernel(
    const float* __restrict__ g1v, const float* __restrict__ beta1,
    float* __restrict__ out)
{
    const int row = blockIdx.x;
    const int t = threadIdx.x;
    __shared__ float red[16];
    const __half2* a = (const __half2*)(g_x1h + (size_t)row * DIMS);
    const __half2* f = (const __half2*)(g_ffh + (size_t)row * DIMS);
    float2 av = __half22float2(a[t]);
    float2 fv = __half22float2(f[t]);
    float y0 = av.x + fv.x;
    float y1 = av.y + fv.y;
    const float invN = 1.0f / 1024.0f;
    float s  = block_sum512(y0 + y1, red);
    float ss = block_sum512(y0*y0 + y1*y1, red);
    float m = s * invN, v = ss * invN - m*m;
    float r = rsqrtf(v + 1e-5f);
    float* o = out + (size_t)row * DIMS;
    o[2*t]   = (y0 - m) * r * g1v[2*t]   + beta1[2*t];
    o[2*t+1] = (y1 - m) * r * g1v[2*t+1] + beta1[2*t+1];
}

// ---------------- launch ----------------
extern "C" void kernel_launch(void* const* d_in, const int* in_sizes, int n_in,
                              void* d_out, int out_size)
{
    const float* x     = (const float*)d_in[0];
    const float* Wq    = (const float*)d_in[1];
    const float* bq    = (const float*)d_in[2];
    const float* gq    = (const float*)d_in[3];
    const float* betaq = (const float*)d_in[4];
    const float* Wk    = (const float*)d_in[5];
    const float* bk    = (const float*)d_in[6];
    const float* gk    = (const float*)d_in[7];
    const float* betak = (const float*)d_in[8];
    const float* g0    = (const float*)d_in[9];
    const float* beta0 = (const float*)d_in[10];
    const float* W1    = (const float*)d_in[11];
    const float* b1    = (const float*)d_in[12];
    const float* W2    = (const float*)d_in[13];
    const float* b2    = (const float*)d_in[14];
    const float* g1    = (const float*)d_in[15];
    const float* beta1 = (const float*)d_in[16];
    float* out = (float*)d_out;

    float *pbr;
    __half *pqkh, *px1h, *ph, *pxh, *pwh, *pffh;
    cudaGetSymbolAddress((void**)&pqkh, g_qkh);
    cudaGetSymbolAddress((void**)&px1h, g_x1h);
    cudaGetSymbolAddress((void**)&ph,   g_h);
    cudaGetSymbolAddress((void**)&pffh, g_ffh);
    cudaGetSymbolAddress((void**)&pxh,  g_xh);
    cudaGetSymbolAddress((void**)&pwh,  g_wh);
    cudaGetSymbolAddress((void**)&pbr,  g_br);

    const int SMEM = NSTAGE * STAGE_BYTES;  // 221184 B
    cudaFuncSetAttribute(gemm_h<0,__half>, cudaFuncAttributeMaxDynamicSharedMemorySize, SMEM);
    cudaFuncSetAttribute(gemm_h<1,__half>, cudaFuncAttributeMaxDynamicSharedMemorySize, SMEM);

    // all fp32->fp16 conversions + bias pack in one launch
    conv_all_kernel<<<CONV_BLOCKS, 256>>>(x, Wq, Wk, W1, W2, bq, bk, pxh, pwh);

    // [q|k] = x @ [Wq|Wk]^T + [bq|bk]   (fused, N=2048, fp16 out)
    gemm_h<0,__half><<<dim3(2*DIMS/128, ROWS/256), 256, SMEM>>>(pxh, pwh + WQK_OFF, pbr, pqkh, 2*DIMS, DIMS);
    // LN(q), LN(k), forward FFTs (3 per 2 rows), Kx, Qf
    fft_fwd_kernel<<<ROWS/2, 256>>>(x, gq, betaq, gk, betak);
    // S = sum_s Kx (two-stage, coalesced + parallel)
    reduce_s1_kernel<<<dim3(BATCH, 9, SCHUNK), 256>>>();
    reduce_s2_kernel<<<dim3(BATCH, 9), 64>>>();
    // mix = irfft x2 rows per FFT; x1 = LN(x + mix) -> fp16
    fft_inv_ln_kernel<<<ROWS/2, 256>>>(x, g0, beta0);
    // h = relu(x1 @ W1^T + b1) -> fp16
    gemm_h<1,__half><<<dim3(FFD/128, ROWS/256), 256, SMEM>>>(px1h, pwh + W1_OFF, b1, ph, FFD, DIMS);
    // ff = h @ W2^T + b2 -> fp16
    gemm_h<0,__half><<<dim3(DIMS/128, ROWS/256), 256, SMEM>>>(ph, pwh + W2_OFF, b2, pffh, DIMS, FFD);
    // out = LN(x1 + ff)
    resid_ln_kernel<<<ROWS, 512>>>(g1, beta1, out);
}